// round 3
// baseline (speedup 1.0000x reference)
#include <cuda_runtime.h>

#define QLEN   1024
#define KLEN   2048
#define NHEAD  16
#define DHEAD  64
#define BSZ    4
#define DMODEL 1024
#define MROWS  (QLEN * BSZ)   // 4096 merged (i,b) rows

// ---------------- scratch (static __device__ arrays, no runtime alloc) ----------------
__device__ float g_rhk[KLEN * DMODEL];              // r_head_k  [j][n*64+d]   (8 MB)
__device__ float g_B[NHEAD * MROWS * KLEN];         // B         [n][i*4+b][j] (512 MB)
__device__ float g_C[KLEN * NHEAD];                 // C[j][n]
__device__ float g_D[KLEN * NHEAD];                 // D[j'][n]

// ---------------- generic NT GEMM: C[m][n] = sum_k A[m][k]*B[n][k] ----------------
// BM=BN=128, BK=16, 256 threads, 8x8 micro-tile. M%128==0, N%128==0, K%16==0 assumed.
__global__ __launch_bounds__(256)
void gemm_nt(const float* __restrict__ A, const float* __restrict__ B,
             float* __restrict__ C,
             int K, int lda, int ldb, int ldc,
             long long sA, long long sB, long long sC)
{
    A += (long long)blockIdx.z * sA;
    B += (long long)blockIdx.z * sB;
    C += (long long)blockIdx.z * sC;

    __shared__ float As[16][132];
    __shared__ float Bs[16][132];

    const int t  = threadIdx.x;
    const int m0 = blockIdx.y * 128;
    const int n0 = blockIdx.x * 128;
    const int lr = t >> 2;          // 0..63
    const int lk = (t & 3) << 2;    // 0,4,8,12
    const int tx = t & 15;
    const int ty = t >> 4;

    const float* Ap0 = A + (long long)(m0 + lr) * lda + lk;
    const float* Ap1 = A + (long long)(m0 + lr + 64) * lda + lk;
    const float* Bp0 = B + (long long)(n0 + lr) * ldb + lk;
    const float* Bp1 = B + (long long)(n0 + lr + 64) * ldb + lk;

    float acc[8][8];
#pragma unroll
    for (int i = 0; i < 8; i++)
#pragma unroll
        for (int j = 0; j < 8; j++) acc[i][j] = 0.f;

    for (int k0 = 0; k0 < K; k0 += 16) {
        float4 a0 = *(const float4*)(Ap0 + k0);
        float4 a1 = *(const float4*)(Ap1 + k0);
        float4 b0 = *(const float4*)(Bp0 + k0);
        float4 b1 = *(const float4*)(Bp1 + k0);
        __syncthreads();
        As[lk+0][lr]    = a0.x; As[lk+1][lr]    = a0.y; As[lk+2][lr]    = a0.z; As[lk+3][lr]    = a0.w;
        As[lk+0][lr+64] = a1.x; As[lk+1][lr+64] = a1.y; As[lk+2][lr+64] = a1.z; As[lk+3][lr+64] = a1.w;
        Bs[lk+0][lr]    = b0.x; Bs[lk+1][lr]    = b0.y; Bs[lk+2][lr]    = b0.z; Bs[lk+3][lr]    = b0.w;
        Bs[lk+0][lr+64] = b1.x; Bs[lk+1][lr+64] = b1.y; Bs[lk+2][lr+64] = b1.z; Bs[lk+3][lr+64] = b1.w;
        __syncthreads();
#pragma unroll
        for (int kk = 0; kk < 16; kk++) {
            float4 a4 = *(const float4*)&As[kk][ty * 8];
            float4 a5 = *(const float4*)&As[kk][ty * 8 + 4];
            float4 b4 = *(const float4*)&Bs[kk][tx * 8];
            float4 b5 = *(const float4*)&Bs[kk][tx * 8 + 4];
            float af[8] = {a4.x, a4.y, a4.z, a4.w, a5.x, a5.y, a5.z, a5.w};
            float bf[8] = {b4.x, b4.y, b4.z, b4.w, b5.x, b5.y, b5.z, b5.w};
#pragma unroll
            for (int i = 0; i < 8; i++)
#pragma unroll
                for (int j = 0; j < 8; j++)
                    acc[i][j] = fmaf(af[i], bf[j], acc[i][j]);
        }
    }

#pragma unroll
    for (int ii = 0; ii < 8; ii++) {
        float* Crow = C + (long long)(m0 + ty * 8 + ii) * ldc + n0 + tx * 8;
        float4 v0 = make_float4(acc[ii][0], acc[ii][1], acc[ii][2], acc[ii][3]);
        float4 v1 = make_float4(acc[ii][4], acc[ii][5], acc[ii][6], acc[ii][7]);
        *(float4*)(Crow)     = v0;
        *(float4*)(Crow + 4) = v1;
    }
}

// ---------------- C[j,n] and D[j,n] bias terms ----------------
// C[j,n] = sum_{b,d} r_w_bias[n,d] * w_head_k[j,b,n,d]
// D[j,n] = sum_d    r_r_bias[n,d] * r_head_k[j,n,d]
__global__ __launch_bounds__(512)
void bias_kernel(const float* __restrict__ whk,
                 const float* __restrict__ rwb,
                 const float* __restrict__ rrb)
{
    const int j = blockIdx.x;
    const int n = threadIdx.x >> 5;   // 16 warps = 16 heads
    const int l = threadIdx.x & 31;

    float s = 0.f;
#pragma unroll
    for (int e = l; e < BSZ * DHEAD; e += 32) {
        int b = e >> 6, d = e & 63;
        s += rwb[n * DHEAD + d] * whk[(((j * BSZ + b) * NHEAD) + n) * DHEAD + d];
    }
    float sd = 0.f;
#pragma unroll
    for (int d = l; d < DHEAD; d += 32)
        sd += rrb[n * DHEAD + d] * g_rhk[j * DMODEL + n * DHEAD + d];

#pragma unroll
    for (int o = 16; o > 0; o >>= 1) {
        s  += __shfl_xor_sync(0xffffffffu, s,  o);
        sd += __shfl_xor_sync(0xffffffffu, sd, o);
    }
    if (l == 0) {
        g_C[j * NHEAD + n] = s;
        g_D[j * NHEAD + n] = sd;
    }
}

// ---------------- rel_shift gather + bias add + (b,n) transpose ----------------
// out[i,j,b,n] = C[j,n] + (jp==0 ? 0 : B[i', jp-1, b, n] + D[jp-1, n])
//   where pos = i*KLEN + j + QLEN, i' = pos/(KLEN+1), jp = pos%(KLEN+1)
// Block: one i, 64 consecutive j, all 64 (b,n). Reads coalesced along j; writes are
// contiguous 256B (b,n) vectors per (i,j) cell via a padded smem transpose.
__global__ __launch_bounds__(256)
void shuffle_kernel(float* __restrict__ out)
{
    __shared__ float sT[64][65];
    const int t  = threadIdx.x;
    const int i  = blockIdx.y;
    const int j0 = blockIdx.x * 64;
    const int jj = t & 31;
    const int cb = t >> 5;            // 0..7

#pragma unroll
    for (int jc = 0; jc < 2; jc++) {
        const int j   = j0 + jc * 32 + jj;
        const int pos = i * KLEN + j + QLEN;
        const int ip  = pos / (KLEN + 1);
        const int jp  = pos - ip * (KLEN + 1);
        const int jq  = jp - 1;
#pragma unroll
        for (int u = 0; u < 8; u++) {
            const int c = cb + u * 8;       // c = b*16 + n (output inner index)
            const int b = c >> 4;
            const int n = c & 15;
            float v = g_C[j * NHEAD + n];
            if (jp != 0) {
                v += g_B[((long long)n * MROWS + (ip * BSZ + b)) * KLEN + jq]
                   + g_D[jq * NHEAD + n];
            }
            sT[jc * 32 + jj][c] = v;
        }
    }
    __syncthreads();

#pragma unroll
    for (int w = 0; w < 4; w++) {
        const int jr = w * 16 + (t >> 4);
        const int c4 = (t & 15) * 4;
        float4 v = make_float4(sT[jr][c4], sT[jr][c4 + 1], sT[jr][c4 + 2], sT[jr][c4 + 3]);
        *(float4*)(out + ((long long)i * KLEN + (j0 + jr)) * 64 + c4) = v;
    }
}

// ---------------- launch ----------------
extern "C" void kernel_launch(void* const* d_in, const int* in_sizes, int n_in,
                              void* d_out, int out_size)
{
    const float* q   = (const float*)d_in[0];  // [1024,4,16,64]
    const float* whk = (const float*)d_in[1];  // [2048,4,16,64]
    const float* r   = (const float*)d_in[2];  // [2048,1024]
    const float* Wr  = (const float*)d_in[3];  // [1024,1024]
    const float* rwb = (const float*)d_in[4];  // [16,64]
    const float* rrb = (const float*)d_in[5];  // [16,64]
    float* out = (float*)d_out;
    (void)in_sizes; (void)n_in; (void)out_size;

    float *p_rhk, *p_B;
    cudaGetSymbolAddress((void**)&p_rhk, g_rhk);
    cudaGetSymbolAddress((void**)&p_B,   g_B);

    // 1) r_head_k[j][nd] = r[j][:] . W_r[nd][:]    (M=2048, N=1024, K=1024)
    dim3 g1(DMODEL / 128, KLEN / 128, 1);
    gemm_nt<<<g1, 256>>>(r, Wr, p_rhk, DMODEL, DMODEL, DMODEL, DMODEL, 0, 0, 0);

    // 2) C[j,n], D[j,n]
    bias_kernel<<<KLEN, 512>>>(whk, rwb, rrb);

    // 3) B[n][(i,b)][j] = q[(i,b),n,:] . rhk[j,n,:]   (per n: M=4096, N=2048, K=64)
    dim3 g2(KLEN / 128, MROWS / 128, NHEAD);
    gemm_nt<<<g2, 256>>>(q, p_rhk, p_B, DHEAD, DMODEL, DMODEL, KLEN,
                         64, 64, (long long)MROWS * KLEN);

    // 4) rel-shift gather + bias + transpose to [i][j][b][n]
    dim3 g3(KLEN / 64, QLEN, 1);
    shuffle_kernel<<<g3, 256>>>(out);
}

// round 4
// speedup vs baseline: 1.2574x; 1.2574x over previous
#include <cuda_runtime.h>

#define QLEN   1024
#define KLEN   2048
#define NHEAD  16
#define DHEAD  64
#define BSZ    4
#define DMODEL 1024
#define MROWS  (QLEN * BSZ)   // 4096 merged (i,b) rows

// ---------------- scratch ----------------
__device__ float g_rhk[KLEN * DMODEL];              // r_head_k  [j][n*64+d]
__device__ float g_B[NHEAD * MROWS * KLEN];         // B         [n][i*4+b][j]
__device__ float g_C[KLEN * NHEAD];                 // C[j][n]
__device__ float g_D[KLEN * NHEAD];                 // D[j'][n]

// ---------------- NT GEMM with packed f32x2 FMA ----------------
// C[m][n] = sum_k A[m][k]*B[n][k]. BM=BN=128, BK=16, 256 threads, 8x8 micro
// computed as 8 (dup-a) x 4 (b-pairs) fma.rn.f32x2.
__global__ __launch_bounds__(256)
void gemm_nt(const float* __restrict__ A, const float* __restrict__ B,
             float* __restrict__ C,
             int K, int lda, int ldb, int ldc,
             long long sA, long long sB, long long sC)
{
    A += (long long)blockIdx.z * sA;
    B += (long long)blockIdx.z * sB;
    C += (long long)blockIdx.z * sC;

    __shared__ __align__(16) float As[16][132];
    __shared__ __align__(16) float Bs[16][132];

    const int t  = threadIdx.x;
    const int m0 = blockIdx.y * 128;
    const int n0 = blockIdx.x * 128;
    const int lr = t >> 2;          // 0..63
    const int lk = (t & 3) << 2;    // 0,4,8,12
    const int tx = t & 15;
    const int ty = t >> 4;

    const float* Ap0 = A + (long long)(m0 + lr) * lda + lk;
    const float* Ap1 = A + (long long)(m0 + lr + 64) * lda + lk;
    const float* Bp0 = B + (long long)(n0 + lr) * ldb + lk;
    const float* Bp1 = B + (long long)(n0 + lr + 64) * ldb + lk;

    unsigned long long acc2[8][4];
#pragma unroll
    for (int i = 0; i < 8; i++)
#pragma unroll
        for (int j = 0; j < 4; j++) acc2[i][j] = 0ull;

    for (int k0 = 0; k0 < K; k0 += 16) {
        float4 a0 = *(const float4*)(Ap0 + k0);
        float4 a1 = *(const float4*)(Ap1 + k0);
        float4 b0 = *(const float4*)(Bp0 + k0);
        float4 b1 = *(const float4*)(Bp1 + k0);
        __syncthreads();
        As[lk+0][lr]    = a0.x; As[lk+1][lr]    = a0.y; As[lk+2][lr]    = a0.z; As[lk+3][lr]    = a0.w;
        As[lk+0][lr+64] = a1.x; As[lk+1][lr+64] = a1.y; As[lk+2][lr+64] = a1.z; As[lk+3][lr+64] = a1.w;
        Bs[lk+0][lr]    = b0.x; Bs[lk+1][lr]    = b0.y; Bs[lk+2][lr]    = b0.z; Bs[lk+3][lr]    = b0.w;
        Bs[lk+0][lr+64] = b1.x; Bs[lk+1][lr+64] = b1.y; Bs[lk+2][lr+64] = b1.z; Bs[lk+3][lr+64] = b1.w;
        __syncthreads();
#pragma unroll
        for (int kk = 0; kk < 16; kk++) {
            float4 a4 = *(const float4*)&As[kk][ty * 8];
            float4 a5 = *(const float4*)&As[kk][ty * 8 + 4];
            double2 bd0 = *(const double2*)&Bs[kk][tx * 8];
            double2 bd1 = *(const double2*)&Bs[kk][tx * 8 + 4];
            unsigned long long bp[4];
            bp[0] = __double_as_longlong(bd0.x);
            bp[1] = __double_as_longlong(bd0.y);
            bp[2] = __double_as_longlong(bd1.x);
            bp[3] = __double_as_longlong(bd1.y);
            float af[8] = {a4.x, a4.y, a4.z, a4.w, a5.x, a5.y, a5.z, a5.w};
#pragma unroll
            for (int i = 0; i < 8; i++) {
                unsigned long long ad;
                asm("mov.b64 %0, {%1, %1};" : "=l"(ad) : "f"(af[i]));
#pragma unroll
                for (int k = 0; k < 4; k++)
                    asm("fma.rn.f32x2 %0, %1, %2, %0;"
                        : "+l"(acc2[i][k]) : "l"(ad), "l"(bp[k]));
            }
        }
    }

#pragma unroll
    for (int ii = 0; ii < 8; ii++) {
        float r[8];
#pragma unroll
        for (int k = 0; k < 4; k++)
            asm("mov.b64 {%0, %1}, %2;" : "=f"(r[2*k]), "=f"(r[2*k+1]) : "l"(acc2[ii][k]));
        float* Crow = C + (long long)(m0 + ty * 8 + ii) * ldc + n0 + tx * 8;
        *(float4*)(Crow)     = make_float4(r[0], r[1], r[2], r[3]);
        *(float4*)(Crow + 4) = make_float4(r[4], r[5], r[6], r[7]);
    }
}

// ---------------- C[j,n] and D[j,n] bias terms ----------------
__global__ __launch_bounds__(512)
void bias_kernel(const float* __restrict__ whk,
                 const float* __restrict__ rwb,
                 const float* __restrict__ rrb)
{
    const int j = blockIdx.x;
    const int n = threadIdx.x >> 5;
    const int l = threadIdx.x & 31;

    float s = 0.f;
#pragma unroll
    for (int e = l; e < BSZ * DHEAD; e += 32) {
        int b = e >> 6, d = e & 63;
        s += rwb[n * DHEAD + d] * whk[(((j * BSZ + b) * NHEAD) + n) * DHEAD + d];
    }
    float sd = 0.f;
#pragma unroll
    for (int d = l; d < DHEAD; d += 32)
        sd += rrb[n * DHEAD + d] * g_rhk[j * DMODEL + n * DHEAD + d];

#pragma unroll
    for (int o = 16; o > 0; o >>= 1) {
        s  += __shfl_xor_sync(0xffffffffu, s,  o);
        sd += __shfl_xor_sync(0xffffffffu, sd, o);
    }
    if (l == 0) {
        g_C[j * NHEAD + n] = s;
        g_D[j * NHEAD + n] = sd;
    }
}

// ---------------- rel_shift gather + bias add + (b,n) transpose ----------------
// out[i,j,b,n] = C[j,n] + (jp==0 ? 0 : B[i', jp-1, b, n] + D[jp-1, n])
// Per-block smem staging of the C+D slice kills the strided scalar LDGs that
// saturated L1 (was 96.3% L1, 35.6% DRAM).
__global__ __launch_bounds__(256)
void shuffle_kernel(float* __restrict__ out)
{
    __shared__ float sT[64][65];
    __shared__ float sCD[64][17];
    __shared__ int   sIpB[64];   // ip * BSZ
    __shared__ int   sJq[64];    // jp-1, or -1 when jp==0

    const int t  = threadIdx.x;
    const int i  = blockIdx.y;
    const int j0 = blockIdx.x * 64;

    // stage C[j,n] + D[jq,n] (coalesced: idx runs over n fastest)
    for (int idx = t; idx < 64 * NHEAD; idx += 256) {
        const int jl = idx >> 4;
        const int n  = idx & 15;
        const int j  = j0 + jl;
        const int pos = i * KLEN + j + QLEN;
        const int ip  = pos / (KLEN + 1);
        const int jp  = pos - ip * (KLEN + 1);
        float v = g_C[j * NHEAD + n];
        if (jp != 0) v += g_D[(jp - 1) * NHEAD + n];
        sCD[jl][n] = v;
        if (n == 0) { sIpB[jl] = ip * BSZ; sJq[jl] = jp - 1; }
    }
    __syncthreads();

    const int jj = t & 31;
    const int cb = t >> 5;            // 0..7

#pragma unroll
    for (int jc = 0; jc < 2; jc++) {
        const int jl  = jc * 32 + jj;
        const int jq  = sJq[jl];
        const int ipb = sIpB[jl];
#pragma unroll
        for (int u = 0; u < 8; u++) {
            const int c = cb + u * 8;       // c = b*16 + n
            const int b = c >> 4;
            const int n = c & 15;
            float v = sCD[jl][n];
            if (jq >= 0)
                v += g_B[((long long)n * MROWS + ipb + b) * KLEN + jq];
            sT[jl][c] = v;
        }
    }
    __syncthreads();

#pragma unroll
    for (int w = 0; w < 4; w++) {
        const int jr = w * 16 + (t >> 4);
        const int c4 = (t & 15) * 4;
        float4 v = make_float4(sT[jr][c4], sT[jr][c4 + 1], sT[jr][c4 + 2], sT[jr][c4 + 3]);
        *(float4*)(out + ((long long)i * KLEN + (j0 + jr)) * 64 + c4) = v;
    }
}

// ---------------- launch ----------------
extern "C" void kernel_launch(void* const* d_in, const int* in_sizes, int n_in,
                              void* d_out, int out_size)
{
    const float* q   = (const float*)d_in[0];
    const float* whk = (const float*)d_in[1];
    const float* r   = (const float*)d_in[2];
    const float* Wr  = (const float*)d_in[3];
    const float* rwb = (const float*)d_in[4];
    const float* rrb = (const float*)d_in[5];
    float* out = (float*)d_out;
    (void)in_sizes; (void)n_in; (void)out_size;

    float *p_rhk, *p_B;
    cudaGetSymbolAddress((void**)&p_rhk, g_rhk);
    cudaGetSymbolAddress((void**)&p_B,   g_B);

    // 1) r_head_k (M=2048, N=1024, K=1024)
    dim3 g1(DMODEL / 128, KLEN / 128, 1);
    gemm_nt<<<g1, 256>>>(r, Wr, p_rhk, DMODEL, DMODEL, DMODEL, DMODEL, 0, 0, 0);

    // 2) C[j,n], D[j,n]
    bias_kernel<<<KLEN, 512>>>(whk, rwb, rrb);

    // 3) B[n][(i,b)][j]  (per head: M=4096, N=2048, K=64)
    dim3 g2(KLEN / 128, MROWS / 128, NHEAD);
    gemm_nt<<<g2, 256>>>(q, p_rhk, p_B, DHEAD, DMODEL, DMODEL, KLEN,
                         64, 64, (long long)MROWS * KLEN);

    // 4) rel-shift gather + bias + transpose
    dim3 g3(KLEN / 64, QLEN, 1);
    shuffle_kernel<<<g3, 256>>>(out);
}

// round 7
// speedup vs baseline: 1.7471x; 1.3895x over previous
#include <cuda_runtime.h>
#include <cuda_bf16.h>
#include <cstdint>

#define QLEN   1024
#define KLEN   2048
#define NHEAD  16
#define DHEAD  64
#define BSZ    4
#define DMODEL 1024
#define MROWS  (QLEN * BSZ)   // 4096 merged (i,b) rows
#define KSEG3  192            // 3*DHEAD
#define KBIG3  3072           // 3*DMODEL

// ---------------- scratch ----------------
__device__ float g_rhk[KLEN * DMODEL];                        // r_head_k [j][n*64+d] fp32
__device__ float g_B[(size_t)NHEAD * MROWS * KLEN];           // B [n][(i,b)][j] fp32 (512MB)
__device__ float g_C[KLEN * NHEAD];
__device__ float g_D[KLEN * NHEAD];
__device__ __nv_bfloat16 g_Abf[(size_t)NHEAD * MROWS * KSEG3]; // q:   [n][(i,b)][ah|ah|al]
__device__ __nv_bfloat16 g_Bbf[(size_t)NHEAD * KLEN * KSEG3];  // rhk: [n][j][bh|bl|bh]
__device__ __nv_bfloat16 g_r3[(size_t)KLEN * KBIG3];           // r:   [j][h|h|l]
__device__ __nv_bfloat16 g_Wr3[(size_t)DMODEL * KBIG3];        // W_r: [nd][h|l|h]

// ---------------- HMMA NT GEMM: C[m][n] = sum_k A[m][k]*B[n][k] (bf16 in, fp32 out)
// CTA tile 128x128, BK=32, 8 warps of 64x32, mma.sync.m16n8k16, double-buffered smem.
#define SPAD 40   // smem row stride in bf16 (20 words: conflict-free frag LDS)

__global__ __launch_bounds__(256)
void gemm_nt_mma(const __nv_bfloat16* __restrict__ A,
                 const __nv_bfloat16* __restrict__ Bm,
                 float* __restrict__ Cout,
                 int K, int ldc,
                 long long sA, long long sB, long long sC)
{
    __shared__ __align__(16) __nv_bfloat16 As[2][128][SPAD];
    __shared__ __align__(16) __nv_bfloat16 Bs[2][128][SPAD];

    A    += (long long)blockIdx.z * sA;
    Bm   += (long long)blockIdx.z * sB;
    Cout += (long long)blockIdx.z * sC;
    const int m0 = blockIdx.y << 7, n0 = blockIdx.x << 7;

    const int t    = threadIdx.x;
    const int lane = t & 31;
    const int wid  = t >> 5;
    const int wm   = (wid & 1) * 64;     // warp m offset
    const int wn   = (wid >> 1) * 32;    // warp n offset
    const int nchunk = K >> 5;

    const int srow0 = t >> 2, sc16 = (t & 3) << 3;
    const int srow1 = srow0 + 64;

    float acc[4][4][4];
#pragma unroll
    for (int f = 0; f < 4; f++)
#pragma unroll
        for (int g = 0; g < 4; g++)
#pragma unroll
            for (int c = 0; c < 4; c++) acc[f][g][c] = 0.f;

    uint4 ra0, ra1, rb0, rb1;
    ra0 = *(const uint4*)(A  + (long long)(m0 + srow0) * K + sc16);
    ra1 = *(const uint4*)(A  + (long long)(m0 + srow1) * K + sc16);
    rb0 = *(const uint4*)(Bm + (long long)(n0 + srow0) * K + sc16);
    rb1 = *(const uint4*)(Bm + (long long)(n0 + srow1) * K + sc16);

    for (int kc = 0; kc < nchunk; kc++) {
        const int buf = kc & 1;
        *(uint4*)&As[buf][srow0][sc16] = ra0;
        *(uint4*)&As[buf][srow1][sc16] = ra1;
        *(uint4*)&Bs[buf][srow0][sc16] = rb0;
        *(uint4*)&Bs[buf][srow1][sc16] = rb1;
        __syncthreads();

        if (kc + 1 < nchunk) {
            const int ko = (kc + 1) << 5;
            ra0 = *(const uint4*)(A  + (long long)(m0 + srow0) * K + ko + sc16);
            ra1 = *(const uint4*)(A  + (long long)(m0 + srow1) * K + ko + sc16);
            rb0 = *(const uint4*)(Bm + (long long)(n0 + srow0) * K + ko + sc16);
            rb1 = *(const uint4*)(Bm + (long long)(n0 + srow1) * K + ko + sc16);
        }

#pragma unroll
        for (int ks = 0; ks < 32; ks += 16) {
            uint32_t af[4][4], bfr[4][2];
            const int kw = ks + ((lane & 3) << 1);
#pragma unroll
            for (int f = 0; f < 4; f++) {
                const int r0 = wm + f * 16 + (lane >> 2);
                const uint32_t* p0 = (const uint32_t*)&As[buf][r0][kw];
                const uint32_t* p1 = (const uint32_t*)&As[buf][r0 + 8][kw];
                af[f][0] = p0[0]; af[f][1] = p1[0];
                af[f][2] = p0[4]; af[f][3] = p1[4];
            }
#pragma unroll
            for (int g = 0; g < 4; g++) {
                const int n = wn + g * 8 + (lane >> 2);
                const uint32_t* pn = (const uint32_t*)&Bs[buf][n][kw];
                bfr[g][0] = pn[0]; bfr[g][1] = pn[4];
            }
#pragma unroll
            for (int f = 0; f < 4; f++)
#pragma unroll
                for (int g = 0; g < 4; g++)
                    asm volatile(
                        "mma.sync.aligned.m16n8k16.row.col.f32.bf16.bf16.f32 "
                        "{%0,%1,%2,%3}, {%4,%5,%6,%7}, {%8,%9}, {%0,%1,%2,%3};"
                        : "+f"(acc[f][g][0]), "+f"(acc[f][g][1]),
                          "+f"(acc[f][g][2]), "+f"(acc[f][g][3])
                        : "r"(af[f][0]), "r"(af[f][1]), "r"(af[f][2]), "r"(af[f][3]),
                          "r"(bfr[g][0]), "r"(bfr[g][1]));
        }
        __syncthreads();
    }

#pragma unroll
    for (int f = 0; f < 4; f++) {
        const int r = m0 + wm + f * 16 + (lane >> 2);
#pragma unroll
        for (int g = 0; g < 4; g++) {
            const int c = n0 + wn + g * 8 + ((lane & 3) << 1);
            *(float2*)(Cout + (long long)r * ldc + c)       = make_float2(acc[f][g][0], acc[f][g][1]);
            *(float2*)(Cout + (long long)(r + 8) * ldc + c) = make_float2(acc[f][g][2], acc[f][g][3]);
        }
    }
}

// ---------------- 3-segment split-bf16 conversions ----------------
// A-side layout: [hi | hi | lo];  B-side layout: [hi | lo | hi]
__global__ __launch_bounds__(256) void conv_q(const float* __restrict__ q) {
    const int r = blockIdx.x;
#pragma unroll
    for (int it = 0; it < 4; it++) {
        int e = threadIdx.x + it * 256;
        int n = e >> 6, d = e & 63;
        float x = q[(long long)r * 1024 + e];
        __nv_bfloat16 hi = __float2bfloat16(x);
        __nv_bfloat16 lo = __float2bfloat16(x - __bfloat162float(hi));
        __nv_bfloat16* dst = g_Abf + ((size_t)n * MROWS + r) * KSEG3;
        dst[d] = hi; dst[64 + d] = hi; dst[128 + d] = lo;
    }
}
__global__ __launch_bounds__(256) void conv_rhk() {
    const int j = blockIdx.x;
#pragma unroll
    for (int it = 0; it < 4; it++) {
        int e = threadIdx.x + it * 256;
        int n = e >> 6, d = e & 63;
        float x = g_rhk[(long long)j * 1024 + e];
        __nv_bfloat16 hi = __float2bfloat16(x);
        __nv_bfloat16 lo = __float2bfloat16(x - __bfloat162float(hi));
        __nv_bfloat16* dst = g_Bbf + ((size_t)n * KLEN + j) * KSEG3;
        dst[d] = hi; dst[64 + d] = lo; dst[128 + d] = hi;
    }
}
// is_b = 0: [hi|hi|lo] ; is_b = 1: [hi|lo|hi]   (1024-wide rows -> 3072-wide rows)
__global__ __launch_bounds__(256) void conv_mat(const float* __restrict__ in,
                                                __nv_bfloat16* __restrict__ outp,
                                                int is_b) {
    const int r = blockIdx.x;
#pragma unroll
    for (int it = 0; it < 4; it++) {
        int e = threadIdx.x + it * 256;
        float x = in[(long long)r * 1024 + e];
        __nv_bfloat16 hi = __float2bfloat16(x);
        __nv_bfloat16 lo = __float2bfloat16(x - __bfloat162float(hi));
        __nv_bfloat16* dst = outp + (size_t)r * KBIG3;
        dst[e] = hi;
        dst[1024 + e] = is_b ? lo : hi;
        dst[2048 + e] = is_b ? hi : lo;
    }
}

// ---------------- C[j,n] and D[j,n] bias terms ----------------
__global__ __launch_bounds__(512)
void bias_kernel(const float* __restrict__ whk,
                 const float* __restrict__ rwb,
                 const float* __restrict__ rrb)
{
    const int j = blockIdx.x;
    const int n = threadIdx.x >> 5;
    const int l = threadIdx.x & 31;

    float s = 0.f;
#pragma unroll
    for (int e = l; e < BSZ * DHEAD; e += 32) {
        int b = e >> 6, d = e & 63;
        s += rwb[n * DHEAD + d] * whk[(((j * BSZ + b) * NHEAD) + n) * DHEAD + d];
    }
    float sd = 0.f;
#pragma unroll
    for (int d = l; d < DHEAD; d += 32)
        sd += rrb[n * DHEAD + d] * g_rhk[j * DMODEL + n * DHEAD + d];

#pragma unroll
    for (int o = 16; o > 0; o >>= 1) {
        s  += __shfl_xor_sync(0xffffffffu, s,  o);
        sd += __shfl_xor_sync(0xffffffffu, sd, o);
    }
    if (l == 0) {
        g_C[j * NHEAD + n] = s;
        g_D[j * NHEAD + n] = sd;
    }
}

// ---------------- rel_shift gather + bias add + (b,n) transpose ----------------
__global__ __launch_bounds__(256)
void shuffle_kernel(float* __restrict__ out)
{
    __shared__ float sT[64][65];
    __shared__ float sCD[64][17];
    __shared__ int   sIpB[64];
    __shared__ int   sJq[64];

    const int t  = threadIdx.x;
    const int i  = blockIdx.y;
    const int j0 = blockIdx.x * 64;

    for (int idx = t; idx < 64 * NHEAD; idx += 256) {
        const int jl = idx >> 4;
        const int n  = idx & 15;
        const int j  = j0 + jl;
        const int pos = i * KLEN + j + QLEN;
        const int ip  = pos / (KLEN + 1);
        const int jp  = pos - ip * (KLEN + 1);
        float v = g_C[j * NHEAD + n];
        if (jp != 0) v += g_D[(jp - 1) * NHEAD + n];
        sCD[jl][n] = v;
        if (n == 0) { sIpB[jl] = ip * BSZ; sJq[jl] = jp - 1; }
    }
    __syncthreads();

    const int jj = t & 31;
    const int cb = t >> 5;

#pragma unroll
    for (int jc = 0; jc < 2; jc++) {
        const int jl  = jc * 32 + jj;
        const int jq  = sJq[jl];
        const int ipb = sIpB[jl];
#pragma unroll
        for (int u = 0; u < 8; u++) {
            const int c = cb + u * 8;   // c = b*16 + n
            const int b = c >> 4;
            const int n = c & 15;
            float v = sCD[jl][n];
            if (jq >= 0)
                v += g_B[((size_t)n * MROWS + ipb + b) * KLEN + jq];
            sT[jl][c] = v;
        }
    }
    __syncthreads();

#pragma unroll
    for (int w = 0; w < 4; w++) {
        const int jr = w * 16 + (t >> 4);
        const int c4 = (t & 15) * 4;
        float4 v = make_float4(sT[jr][c4], sT[jr][c4 + 1], sT[jr][c4 + 2], sT[jr][c4 + 3]);
        *(float4*)(out + ((long long)i * KLEN + (j0 + jr)) * 64 + c4) = v;
    }
}

// ---------------- launch ----------------
extern "C" void kernel_launch(void* const* d_in, const int* in_sizes, int n_in,
                              void* d_out, int out_size)
{
    const float* q   = (const float*)d_in[0];
    const float* whk = (const float*)d_in[1];
    const float* r   = (const float*)d_in[2];
    const float* Wr  = (const float*)d_in[3];
    const float* rwb = (const float*)d_in[4];
    const float* rrb = (const float*)d_in[5];
    float* out = (float*)d_out;
    (void)in_sizes; (void)n_in; (void)out_size;

    float *p_rhk, *p_B;
    __nv_bfloat16 *p_Abf, *p_Bbf, *p_r3, *p_Wr3;
    cudaGetSymbolAddress((void**)&p_rhk, g_rhk);
    cudaGetSymbolAddress((void**)&p_B,   g_B);
    cudaGetSymbolAddress((void**)&p_Abf, g_Abf);
    cudaGetSymbolAddress((void**)&p_Bbf, g_Bbf);
    cudaGetSymbolAddress((void**)&p_r3,  g_r3);
    cudaGetSymbolAddress((void**)&p_Wr3, g_Wr3);

    // 3-segment split-bf16 conversions
    conv_mat<<<KLEN,   256>>>(r,  p_r3, 0);   // A-side
    conv_mat<<<DMODEL, 256>>>(Wr, p_Wr3, 1);  // B-side
    conv_q  <<<MROWS,  256>>>(q);

    // 1) rhk[j][nd] = r.Wr^T   (M=2048, N=1024, K=3072 triple-split)
    gemm_nt_mma<<<dim3(DMODEL / 128, KLEN / 128, 1), 256>>>(
        p_r3, p_Wr3, p_rhk, KBIG3, DMODEL, 0, 0, 0);

    // 2) C[j,n], D[j,n]
    bias_kernel<<<KLEN, 512>>>(whk, rwb, rrb);

    // rhk -> triple-split per head
    conv_rhk<<<KLEN, 256>>>();

    // 3) B[n][(i,b)][j]  (per head: M=4096, N=2048, K=192 triple-split)
    gemm_nt_mma<<<dim3(KLEN / 128, MROWS / 128, NHEAD), 256>>>(
        p_Abf, p_Bbf, p_B, KSEG3, KLEN,
        (long long)MROWS * KSEG3, (long long)KLEN * KSEG3, (long long)MROWS * KLEN);

    // 4) rel-shift gather + bias + transpose
    shuffle_kernel<<<dim3(KLEN / 64, QLEN), 256>>>(out);
}

// round 8
// speedup vs baseline: 1.9533x; 1.1180x over previous
#include <cuda_runtime.h>
#include <cuda_bf16.h>
#include <cuda_fp16.h>
#include <cstdint>

#define QLEN   1024
#define KLEN   2048
#define NHEAD  16
#define DHEAD  64
#define BSZ    4
#define DMODEL 1024
#define MROWS  (QLEN * BSZ)   // 4096 merged (i,b) rows
#define KBIG3  3072           // 3*DMODEL (triple-split rhk GEMM)
#define KSPLIT 4
#define KSLAB  (KBIG3 / KSPLIT)   // 768
#define KH2    128            // 2*DHEAD (fp16 double-split gemm-B)

// ---------------- scratch ----------------
__device__ float g_rhk4[(size_t)KSPLIT * KLEN * DMODEL];      // split-K slabs (32MB)
__device__ float g_rhk[KLEN * DMODEL];                        // r_head_k [j][n*64+d]
__device__ float g_B[(size_t)NHEAD * MROWS * KLEN];           // B [n][(i,b)][j] (512MB)
__device__ float g_C[KLEN * NHEAD];
__device__ float g_D[KLEN * NHEAD];
__device__ __half g_Ah[(size_t)NHEAD * MROWS * KH2];          // q fp16:   [n][(i,b)][hi64|lo64]
__device__ __half g_Bh[(size_t)NHEAD * KLEN * KH2];           // rhk fp16: [n][j][hi64|lo64]
__device__ __nv_bfloat16 g_r3[(size_t)KLEN * KBIG3];          // r bf16:   [j][h|h|l]
__device__ __nv_bfloat16 g_Wr3[(size_t)DMODEL * KBIG3];       // W_r bf16: [nd][h|l|h]

// ---------------- HMMA NT GEMM (templated bf16 / fp16) ----------------
// C[m][n] = sum_k A[m][k]*B[n][k]. CTA 128x128, BK=32, 8 warps of 64x32,
// mma.sync.m16n8k16, double-buffered smem, separate row strides lda/ldb.
#define SPAD 40

template<int IS_HALF>
__global__ __launch_bounds__(256)
void gemm_nt_mma(const uint16_t* __restrict__ A,
                 const uint16_t* __restrict__ Bm,
                 float* __restrict__ Cout,
                 int K, int lda, int ldb, int ldc,
                 long long sA, long long sB, long long sC)
{
    __shared__ __align__(16) uint16_t As[2][128][SPAD];
    __shared__ __align__(16) uint16_t Bs[2][128][SPAD];

    A    += (long long)blockIdx.z * sA;
    Bm   += (long long)blockIdx.z * sB;
    Cout += (long long)blockIdx.z * sC;
    const int m0 = blockIdx.y << 7, n0 = blockIdx.x << 7;

    const int t    = threadIdx.x;
    const int lane = t & 31;
    const int wid  = t >> 5;
    const int wm   = (wid & 1) * 64;
    const int wn   = (wid >> 1) * 32;
    const int nchunk = K >> 5;

    const int srow0 = t >> 2, sc16 = (t & 3) << 3;
    const int srow1 = srow0 + 64;

    const uint16_t* Ab0 = A  + (long long)(m0 + srow0) * lda + sc16;
    const uint16_t* Ab1 = A  + (long long)(m0 + srow1) * lda + sc16;
    const uint16_t* Bb0 = Bm + (long long)(n0 + srow0) * ldb + sc16;
    const uint16_t* Bb1 = Bm + (long long)(n0 + srow1) * ldb + sc16;

    float acc[4][4][4];
#pragma unroll
    for (int f = 0; f < 4; f++)
#pragma unroll
        for (int g = 0; g < 4; g++)
#pragma unroll
            for (int c = 0; c < 4; c++) acc[f][g][c] = 0.f;

    uint4 ra0 = *(const uint4*)Ab0;
    uint4 ra1 = *(const uint4*)Ab1;
    uint4 rb0 = *(const uint4*)Bb0;
    uint4 rb1 = *(const uint4*)Bb1;

    for (int kc = 0; kc < nchunk; kc++) {
        const int buf = kc & 1;
        *(uint4*)&As[buf][srow0][sc16] = ra0;
        *(uint4*)&As[buf][srow1][sc16] = ra1;
        *(uint4*)&Bs[buf][srow0][sc16] = rb0;
        *(uint4*)&Bs[buf][srow1][sc16] = rb1;
        __syncthreads();

        if (kc + 1 < nchunk) {
            const int ko = (kc + 1) << 5;
            ra0 = *(const uint4*)(Ab0 + ko);
            ra1 = *(const uint4*)(Ab1 + ko);
            rb0 = *(const uint4*)(Bb0 + ko);
            rb1 = *(const uint4*)(Bb1 + ko);
        }

#pragma unroll
        for (int ks = 0; ks < 32; ks += 16) {
            uint32_t af[4][4], bfr[4][2];
            const int kw = ks + ((lane & 3) << 1);
#pragma unroll
            for (int f = 0; f < 4; f++) {
                const int r0 = wm + f * 16 + (lane >> 2);
                const uint32_t* p0 = (const uint32_t*)&As[buf][r0][kw];
                const uint32_t* p1 = (const uint32_t*)&As[buf][r0 + 8][kw];
                af[f][0] = p0[0]; af[f][1] = p1[0];
                af[f][2] = p0[4]; af[f][3] = p1[4];
            }
#pragma unroll
            for (int g = 0; g < 4; g++) {
                const int n = wn + g * 8 + (lane >> 2);
                const uint32_t* pn = (const uint32_t*)&Bs[buf][n][kw];
                bfr[g][0] = pn[0]; bfr[g][1] = pn[4];
            }
#pragma unroll
            for (int f = 0; f < 4; f++)
#pragma unroll
                for (int g = 0; g < 4; g++) {
                    if (IS_HALF)
                        asm volatile(
                            "mma.sync.aligned.m16n8k16.row.col.f32.f16.f16.f32 "
                            "{%0,%1,%2,%3}, {%4,%5,%6,%7}, {%8,%9}, {%0,%1,%2,%3};"
                            : "+f"(acc[f][g][0]), "+f"(acc[f][g][1]),
                              "+f"(acc[f][g][2]), "+f"(acc[f][g][3])
                            : "r"(af[f][0]), "r"(af[f][1]), "r"(af[f][2]), "r"(af[f][3]),
                              "r"(bfr[g][0]), "r"(bfr[g][1]));
                    else
                        asm volatile(
                            "mma.sync.aligned.m16n8k16.row.col.f32.bf16.bf16.f32 "
                            "{%0,%1,%2,%3}, {%4,%5,%6,%7}, {%8,%9}, {%0,%1,%2,%3};"
                            : "+f"(acc[f][g][0]), "+f"(acc[f][g][1]),
                              "+f"(acc[f][g][2]), "+f"(acc[f][g][3])
                            : "r"(af[f][0]), "r"(af[f][1]), "r"(af[f][2]), "r"(af[f][3]),
                              "r"(bfr[g][0]), "r"(bfr[g][1]));
                }
        }
        __syncthreads();
    }

#pragma unroll
    for (int f = 0; f < 4; f++) {
        const int r = m0 + wm + f * 16 + (lane >> 2);
#pragma unroll
        for (int g = 0; g < 4; g++) {
            const int c = n0 + wn + g * 8 + ((lane & 3) << 1);
            *(float2*)(Cout + (long long)r * ldc + c)       = make_float2(acc[f][g][0], acc[f][g][1]);
            *(float2*)(Cout + (long long)(r + 8) * ldc + c) = make_float2(acc[f][g][2], acc[f][g][3]);
        }
    }
}

// ---------------- split-K slab reduce (deterministic) ----------------
__global__ __launch_bounds__(256) void reduce4() {
    const size_t i = ((size_t)blockIdx.x * 256 + threadIdx.x) * 4;
    float4 a = *(const float4*)&g_rhk4[i];
    float4 b = *(const float4*)&g_rhk4[i + (size_t)KLEN * DMODEL];
    float4 c = *(const float4*)&g_rhk4[i + (size_t)2 * KLEN * DMODEL];
    float4 d = *(const float4*)&g_rhk4[i + (size_t)3 * KLEN * DMODEL];
    *(float4*)&g_rhk[i] = make_float4(a.x + b.x + c.x + d.x, a.y + b.y + c.y + d.y,
                                      a.z + b.z + c.z + d.z, a.w + b.w + c.w + d.w);
}

// ---------------- conversions ----------------
// bf16 triple-split for rhk GEMM.  is_b=0: [hi|hi|lo], is_b=1: [hi|lo|hi]
__global__ __launch_bounds__(256) void conv_mat(const float* __restrict__ in,
                                                __nv_bfloat16* __restrict__ outp,
                                                int is_b) {
    const int r = blockIdx.x;
#pragma unroll
    for (int it = 0; it < 4; it++) {
        int e = threadIdx.x + it * 256;
        float x = in[(long long)r * 1024 + e];
        __nv_bfloat16 hi = __float2bfloat16(x);
        __nv_bfloat16 lo = __float2bfloat16(x - __bfloat162float(hi));
        __nv_bfloat16* dst = outp + (size_t)r * KBIG3;
        dst[e] = hi;
        dst[1024 + e] = is_b ? lo : hi;
        dst[2048 + e] = is_b ? hi : lo;
    }
}
// fp16 double-split of q: [n][(i,b)][hi64|lo64]
__global__ __launch_bounds__(256) void conv_q_h(const float* __restrict__ q) {
    const int r = blockIdx.x;
#pragma unroll
    for (int it = 0; it < 4; it++) {
        int e = threadIdx.x + it * 256;
        int n = e >> 6, d = e & 63;
        float x = q[(long long)r * 1024 + e];
        __half hi = __float2half_rn(x);
        __half lo = __float2half_rn(x - __half2float(hi));
        __half* dst = g_Ah + ((size_t)n * MROWS + r) * KH2;
        dst[d] = hi;
        dst[64 + d] = lo;
    }
}
// fp16 double-split of rhk: [n][j][hi64|lo64]
__global__ __launch_bounds__(256) void conv_rhk_h() {
    const int j = blockIdx.x;
#pragma unroll
    for (int it = 0; it < 4; it++) {
        int e = threadIdx.x + it * 256;
        int n = e >> 6, d = e & 63;
        float x = g_rhk[(long long)j * 1024 + e];
        __half hi = __float2half_rn(x);
        __half lo = __float2half_rn(x - __half2float(hi));
        __half* dst = g_Bh + ((size_t)n * KLEN + j) * KH2;
        dst[d] = hi;
        dst[64 + d] = lo;
    }
}

// ---------------- C[j,n] and D[j,n] bias terms ----------------
__global__ __launch_bounds__(512)
void bias_kernel(const float* __restrict__ whk,
                 const float* __restrict__ rwb,
                 const float* __restrict__ rrb)
{
    const int j = blockIdx.x;
    const int n = threadIdx.x >> 5;
    const int l = threadIdx.x & 31;

    float s = 0.f;
#pragma unroll
    for (int e = l; e < BSZ * DHEAD; e += 32) {
        int b = e >> 6, d = e & 63;
        s += rwb[n * DHEAD + d] * whk[(((j * BSZ + b) * NHEAD) + n) * DHEAD + d];
    }
    float sd = 0.f;
#pragma unroll
    for (int d = l; d < DHEAD; d += 32)
        sd += rrb[n * DHEAD + d] * g_rhk[j * DMODEL + n * DHEAD + d];

#pragma unroll
    for (int o = 16; o > 0; o >>= 1) {
        s  += __shfl_xor_sync(0xffffffffu, s,  o);
        sd += __shfl_xor_sync(0xffffffffu, sd, o);
    }
    if (l == 0) {
        g_C[j * NHEAD + n] = s;
        g_D[j * NHEAD + n] = sd;
    }
}

// ---------------- rel_shift gather + bias add + (b,n) transpose ----------------
__global__ __launch_bounds__(256)
void shuffle_kernel(float* __restrict__ out)
{
    __shared__ float sT[64][65];
    __shared__ float sCD[64][17];
    __shared__ int   sIpB[64];
    __shared__ int   sJq[64];

    const int t  = threadIdx.x;
    const int i  = blockIdx.y;
    const int j0 = blockIdx.x * 64;

    for (int idx = t; idx < 64 * NHEAD; idx += 256) {
        const int jl = idx >> 4;
        const int n  = idx & 15;
        const int j  = j0 + jl;
        const int pos = i * KLEN + j + QLEN;
        const int ip  = pos / (KLEN + 1);
        const int jp  = pos - ip * (KLEN + 1);
        float v = g_C[j * NHEAD + n];
        if (jp != 0) v += g_D[(jp - 1) * NHEAD + n];
        sCD[jl][n] = v;
        if (n == 0) { sIpB[jl] = ip * BSZ; sJq[jl] = jp - 1; }
    }
    __syncthreads();

    const int jj = t & 31;
    const int cb = t >> 5;

#pragma unroll
    for (int jc = 0; jc < 2; jc++) {
        const int jl  = jc * 32 + jj;
        const int jq  = sJq[jl];
        const int ipb = sIpB[jl];
#pragma unroll
        for (int u = 0; u < 8; u++) {
            const int c = cb + u * 8;   // c = b*16 + n
            const int b = c >> 4;
            const int n = c & 15;
            float v = sCD[jl][n];
            if (jq >= 0)
                v += g_B[((size_t)n * MROWS + ipb + b) * KLEN + jq];
            sT[jl][c] = v;
        }
    }
    __syncthreads();

#pragma unroll
    for (int w = 0; w < 4; w++) {
        const int jr = w * 16 + (t >> 4);
        const int c4 = (t & 15) * 4;
        float4 v = make_float4(sT[jr][c4], sT[jr][c4 + 1], sT[jr][c4 + 2], sT[jr][c4 + 3]);
        *(float4*)(out + ((long long)i * KLEN + (j0 + jr)) * 64 + c4) = v;
    }
}

// ---------------- launch ----------------
extern "C" void kernel_launch(void* const* d_in, const int* in_sizes, int n_in,
                              void* d_out, int out_size)
{
    const float* q   = (const float*)d_in[0];
    const float* whk = (const float*)d_in[1];
    const float* r   = (const float*)d_in[2];
    const float* Wr  = (const float*)d_in[3];
    const float* rwb = (const float*)d_in[4];
    const float* rrb = (const float*)d_in[5];
    float* out = (float*)d_out;
    (void)in_sizes; (void)n_in; (void)out_size;

    float *p_rhk4, *p_B;
    __half *p_Ah, *p_Bh;
    __nv_bfloat16 *p_r3, *p_Wr3;
    cudaGetSymbolAddress((void**)&p_rhk4, g_rhk4);
    cudaGetSymbolAddress((void**)&p_B,    g_B);
    cudaGetSymbolAddress((void**)&p_Ah,   g_Ah);
    cudaGetSymbolAddress((void**)&p_Bh,   g_Bh);
    cudaGetSymbolAddress((void**)&p_r3,   g_r3);
    cudaGetSymbolAddress((void**)&p_Wr3,  g_Wr3);

    // conversions
    conv_mat<<<KLEN,   256>>>(r,  p_r3, 0);   // A-side [h|h|l]
    conv_mat<<<DMODEL, 256>>>(Wr, p_Wr3, 1);  // B-side [h|l|h]
    conv_q_h<<<MROWS,  256>>>(q);

    // 1) rhk = r.Wr^T, bf16 triple-split, split-K=4 slabs (M=2048,N=1024,K=768 each)
    gemm_nt_mma<0><<<dim3(DMODEL / 128, KLEN / 128, KSPLIT), 256>>>(
        (const uint16_t*)p_r3, (const uint16_t*)p_Wr3, p_rhk4,
        KSLAB, KBIG3, KBIG3, DMODEL,
        KSLAB, KSLAB, (long long)KLEN * DMODEL);
    reduce4<<<(KLEN * DMODEL) / (256 * 4), 256>>>();

    // 2) C[j,n], D[j,n]
    bias_kernel<<<KLEN, 512>>>(whk, rwb, rrb);

    // rhk -> fp16 double-split per head
    conv_rhk_h<<<KLEN, 256>>>();

    // 3) B[n][(i,b)][j]  (per head: M=4096, N=2048, K=128 fp16 double-split)
    gemm_nt_mma<1><<<dim3(KLEN / 128, MROWS / 128, NHEAD), 256>>>(
        (const uint16_t*)p_Ah, (const uint16_t*)p_Bh, p_B,
        KH2, KH2, KH2, KLEN,
        (long long)MROWS * KH2, (long long)KLEN * KH2, (long long)MROWS * KLEN);

    // 4) rel-shift gather + bias + transpose
    shuffle_kernel<<<dim3(KLEN / 64, QLEN), 256>>>(out);
}

// round 9
// speedup vs baseline: 2.0408x; 1.0448x over previous
#include <cuda_runtime.h>
#include <cuda_bf16.h>
#include <cuda_fp16.h>
#include <cstdint>

#define QLEN   1024
#define KLEN   2048
#define NHEAD  16
#define DHEAD  64
#define BSZ    4
#define DMODEL 1024
#define MROWS  (QLEN * BSZ)   // 4096 merged (i,b) rows
#define KBIG3  3072           // 3*DMODEL (triple-split rhk GEMM)
#define KSPLIT 4
#define KSLAB  (KBIG3 / KSPLIT)   // 768
#define KH2    128            // 2*DHEAD (fp16 double-split gemm-B)

// ---------------- scratch ----------------
__device__ float g_rhk4[(size_t)KSPLIT * KLEN * DMODEL];      // split-K slabs (32MB)
__device__ float g_rhk[KLEN * DMODEL];                        // r_head_k [j][n*64+d]
__device__ __half g_B16[(size_t)NHEAD * MROWS * KLEN];        // B [n][(i,b)][j] fp16 (256MB)
__device__ float g_C[KLEN * NHEAD];
__device__ float g_D[KLEN * NHEAD];
__device__ __half g_Ah[(size_t)NHEAD * MROWS * KH2];          // q fp16:   [n][(i,b)][hi64|lo64]
__device__ __half g_Bh[(size_t)NHEAD * KLEN * KH2];           // rhk fp16: [n][j][hi64|lo64]
__device__ __nv_bfloat16 g_r3[(size_t)KLEN * KBIG3];          // r bf16:   [j][h|h|l]
__device__ __nv_bfloat16 g_Wr3[(size_t)DMODEL * KBIG3];       // W_r bf16: [nd][h|l|h]

// ---------------- HMMA NT GEMM (templated dtype + output precision) ----------------
// C[m][n] = sum_k A[m][k]*B[n][k]. CTA 128x128, BK=32, 8 warps of 64x32,
// mma.sync.m16n8k16, double-buffered smem.
#define SPAD 40

template<int IS_HALF, int OUT_HALF>
__global__ __launch_bounds__(256)
void gemm_nt_mma(const uint16_t* __restrict__ A,
                 const uint16_t* __restrict__ Bm,
                 void* __restrict__ CoutV,
                 int K, int lda, int ldb, int ldc,
                 long long sA, long long sB, long long sC)
{
    __shared__ __align__(16) uint16_t As[2][128][SPAD];
    __shared__ __align__(16) uint16_t Bs[2][128][SPAD];

    A  += (long long)blockIdx.z * sA;
    Bm += (long long)blockIdx.z * sB;
    const int m0 = blockIdx.y << 7, n0 = blockIdx.x << 7;

    const int t    = threadIdx.x;
    const int lane = t & 31;
    const int wid  = t >> 5;
    const int wm   = (wid & 1) * 64;
    const int wn   = (wid >> 1) * 32;
    const int nchunk = K >> 5;

    const int srow0 = t >> 2, sc16 = (t & 3) << 3;
    const int srow1 = srow0 + 64;

    const uint16_t* Ab0 = A  + (long long)(m0 + srow0) * lda + sc16;
    const uint16_t* Ab1 = A  + (long long)(m0 + srow1) * lda + sc16;
    const uint16_t* Bb0 = Bm + (long long)(n0 + srow0) * ldb + sc16;
    const uint16_t* Bb1 = Bm + (long long)(n0 + srow1) * ldb + sc16;

    float acc[4][4][4];
#pragma unroll
    for (int f = 0; f < 4; f++)
#pragma unroll
        for (int g = 0; g < 4; g++)
#pragma unroll
            for (int c = 0; c < 4; c++) acc[f][g][c] = 0.f;

    uint4 ra0 = *(const uint4*)Ab0;
    uint4 ra1 = *(const uint4*)Ab1;
    uint4 rb0 = *(const uint4*)Bb0;
    uint4 rb1 = *(const uint4*)Bb1;

    for (int kc = 0; kc < nchunk; kc++) {
        const int buf = kc & 1;
        *(uint4*)&As[buf][srow0][sc16] = ra0;
        *(uint4*)&As[buf][srow1][sc16] = ra1;
        *(uint4*)&Bs[buf][srow0][sc16] = rb0;
        *(uint4*)&Bs[buf][srow1][sc16] = rb1;
        __syncthreads();

        if (kc + 1 < nchunk) {
            const int ko = (kc + 1) << 5;
            ra0 = *(const uint4*)(Ab0 + ko);
            ra1 = *(const uint4*)(Ab1 + ko);
            rb0 = *(const uint4*)(Bb0 + ko);
            rb1 = *(const uint4*)(Bb1 + ko);
        }

#pragma unroll
        for (int ks = 0; ks < 32; ks += 16) {
            uint32_t af[4][4], bfr[4][2];
            const int kw = ks + ((lane & 3) << 1);
#pragma unroll
            for (int f = 0; f < 4; f++) {
                const int r0 = wm + f * 16 + (lane >> 2);
                const uint32_t* p0 = (const uint32_t*)&As[buf][r0][kw];
                const uint32_t* p1 = (const uint32_t*)&As[buf][r0 + 8][kw];
                af[f][0] = p0[0]; af[f][1] = p1[0];
                af[f][2] = p0[4]; af[f][3] = p1[4];
            }
#pragma unroll
            for (int g = 0; g < 4; g++) {
                const int n = wn + g * 8 + (lane >> 2);
                const uint32_t* pn = (const uint32_t*)&Bs[buf][n][kw];
                bfr[g][0] = pn[0]; bfr[g][1] = pn[4];
            }
#pragma unroll
            for (int f = 0; f < 4; f++)
#pragma unroll
                for (int g = 0; g < 4; g++) {
                    if (IS_HALF)
                        asm volatile(
                            "mma.sync.aligned.m16n8k16.row.col.f32.f16.f16.f32 "
                            "{%0,%1,%2,%3}, {%4,%5,%6,%7}, {%8,%9}, {%0,%1,%2,%3};"
                            : "+f"(acc[f][g][0]), "+f"(acc[f][g][1]),
                              "+f"(acc[f][g][2]), "+f"(acc[f][g][3])
                            : "r"(af[f][0]), "r"(af[f][1]), "r"(af[f][2]), "r"(af[f][3]),
                              "r"(bfr[g][0]), "r"(bfr[g][1]));
                    else
                        asm volatile(
                            "mma.sync.aligned.m16n8k16.row.col.f32.bf16.bf16.f32 "
                            "{%0,%1,%2,%3}, {%4,%5,%6,%7}, {%8,%9}, {%0,%1,%2,%3};"
                            : "+f"(acc[f][g][0]), "+f"(acc[f][g][1]),
                              "+f"(acc[f][g][2]), "+f"(acc[f][g][3])
                            : "r"(af[f][0]), "r"(af[f][1]), "r"(af[f][2]), "r"(af[f][3]),
                              "r"(bfr[g][0]), "r"(bfr[g][1]));
                }
        }
        __syncthreads();
    }

    if (OUT_HALF) {
        __half* Cout = (__half*)CoutV + (long long)blockIdx.z * sC;
#pragma unroll
        for (int f = 0; f < 4; f++) {
            const int r = m0 + wm + f * 16 + (lane >> 2);
#pragma unroll
            for (int g = 0; g < 4; g++) {
                const int c = n0 + wn + g * 8 + ((lane & 3) << 1);
                __half2 h0 = __floats2half2_rn(acc[f][g][0], acc[f][g][1]);
                __half2 h1 = __floats2half2_rn(acc[f][g][2], acc[f][g][3]);
                *(__half2*)(Cout + (long long)r * ldc + c)       = h0;
                *(__half2*)(Cout + (long long)(r + 8) * ldc + c) = h1;
            }
        }
    } else {
        float* Cout = (float*)CoutV + (long long)blockIdx.z * sC;
#pragma unroll
        for (int f = 0; f < 4; f++) {
            const int r = m0 + wm + f * 16 + (lane >> 2);
#pragma unroll
            for (int g = 0; g < 4; g++) {
                const int c = n0 + wn + g * 8 + ((lane & 3) << 1);
                *(float2*)(Cout + (long long)r * ldc + c)       = make_float2(acc[f][g][0], acc[f][g][1]);
                *(float2*)(Cout + (long long)(r + 8) * ldc + c) = make_float2(acc[f][g][2], acc[f][g][3]);
            }
        }
    }
}

// ---------------- split-K reduce fused with rhk -> fp16 double-split ----------------
// Writes g_rhk (fp32, for bias D) and g_Bh (fp16 2-seg per head, for gemm-B).
__global__ __launch_bounds__(256) void reduce4_conv() {
    const size_t i = ((size_t)blockIdx.x * 256 + threadIdx.x) * 4;
    float4 a = *(const float4*)&g_rhk4[i];
    float4 b = *(const float4*)&g_rhk4[i + (size_t)KLEN * DMODEL];
    float4 c = *(const float4*)&g_rhk4[i + (size_t)2 * KLEN * DMODEL];
    float4 d = *(const float4*)&g_rhk4[i + (size_t)3 * KLEN * DMODEL];
    float4 s = make_float4(a.x + b.x + c.x + d.x, a.y + b.y + c.y + d.y,
                           a.z + b.z + c.z + d.z, a.w + b.w + c.w + d.w);
    *(float4*)&g_rhk[i] = s;

    const int j = (int)(i >> 10);          // row
    const int e = (int)(i & 1023);         // col (multiple of 4)
    const int n = e >> 6, d0 = e & 63;
    __half* dst = g_Bh + ((size_t)n * KLEN + j) * KH2;
    float v[4] = {s.x, s.y, s.z, s.w};
    __half hi[4], lo[4];
#pragma unroll
    for (int u = 0; u < 4; u++) {
        hi[u] = __float2half_rn(v[u]);
        lo[u] = __float2half_rn(v[u] - __half2float(hi[u]));
    }
    *(__half2*)(dst + d0)          = __halves2half2(hi[0], hi[1]);
    *(__half2*)(dst + d0 + 2)      = __halves2half2(hi[2], hi[3]);
    *(__half2*)(dst + 64 + d0)     = __halves2half2(lo[0], lo[1]);
    *(__half2*)(dst + 64 + d0 + 2) = __halves2half2(lo[2], lo[3]);
}

// ---------------- conversions ----------------
// bf16 triple-split for rhk GEMM.  is_b=0: [hi|hi|lo], is_b=1: [hi|lo|hi]
__global__ __launch_bounds__(256) void conv_mat(const float* __restrict__ in,
                                                __nv_bfloat16* __restrict__ outp,
                                                int is_b) {
    const int r = blockIdx.x;
#pragma unroll
    for (int it = 0; it < 4; it++) {
        int e = threadIdx.x + it * 256;
        float x = in[(long long)r * 1024 + e];
        __nv_bfloat16 hi = __float2bfloat16(x);
        __nv_bfloat16 lo = __float2bfloat16(x - __bfloat162float(hi));
        __nv_bfloat16* dst = outp + (size_t)r * KBIG3;
        dst[e] = hi;
        dst[1024 + e] = is_b ? lo : hi;
        dst[2048 + e] = is_b ? hi : lo;
    }
}
// fp16 double-split of q: [n][(i,b)][hi64|lo64]
__global__ __launch_bounds__(256) void conv_q_h(const float* __restrict__ q) {
    const int r = blockIdx.x;
#pragma unroll
    for (int it = 0; it < 4; it++) {
        int e = threadIdx.x + it * 256;
        int n = e >> 6, d = e & 63;
        float x = q[(long long)r * 1024 + e];
        __half hi = __float2half_rn(x);
        __half lo = __float2half_rn(x - __half2float(hi));
        __half* dst = g_Ah + ((size_t)n * MROWS + r) * KH2;
        dst[d] = hi;
        dst[64 + d] = lo;
    }
}

// ---------------- C[j,n] and D[j,n] bias terms ----------------
__global__ __launch_bounds__(512)
void bias_kernel(const float* __restrict__ whk,
                 const float* __restrict__ rwb,
                 const float* __restrict__ rrb)
{
    const int j = blockIdx.x;
    const int n = threadIdx.x >> 5;
    const int l = threadIdx.x & 31;

    float s = 0.f;
#pragma unroll
    for (int e = l; e < BSZ * DHEAD; e += 32) {
        int b = e >> 6, d = e & 63;
        s += rwb[n * DHEAD + d] * whk[(((j * BSZ + b) * NHEAD) + n) * DHEAD + d];
    }
    float sd = 0.f;
#pragma unroll
    for (int d = l; d < DHEAD; d += 32)
        sd += rrb[n * DHEAD + d] * g_rhk[j * DMODEL + n * DHEAD + d];

#pragma unroll
    for (int o = 16; o > 0; o >>= 1) {
        s  += __shfl_xor_sync(0xffffffffu, s,  o);
        sd += __shfl_xor_sync(0xffffffffu, sd, o);
    }
    if (l == 0) {
        g_C[j * NHEAD + n] = s;
        g_D[j * NHEAD + n] = sd;
    }
}

// ---------------- rel_shift gather + bias add + (b,n) transpose ----------------
__global__ __launch_bounds__(256)
void shuffle_kernel(float* __restrict__ out)
{
    __shared__ float sT[64][65];
    __shared__ float sCD[64][17];
    __shared__ int   sIpB[64];
    __shared__ int   sJq[64];

    const int t  = threadIdx.x;
    const int i  = blockIdx.y;
    const int j0 = blockIdx.x * 64;

    for (int idx = t; idx < 64 * NHEAD; idx += 256) {
        const int jl = idx >> 4;
        const int n  = idx & 15;
        const int j  = j0 + jl;
        const int pos = i * KLEN + j + QLEN;
        const int ip  = pos / (KLEN + 1);
        const int jp  = pos - ip * (KLEN + 1);
        float v = g_C[j * NHEAD + n];
        if (jp != 0) v += g_D[(jp - 1) * NHEAD + n];
        sCD[jl][n] = v;
        if (n == 0) { sIpB[jl] = ip * BSZ; sJq[jl] = jp - 1; }
    }
    __syncthreads();

    const int jj = t & 31;
    const int cb = t >> 5;

#pragma unroll
    for (int jc = 0; jc < 2; jc++) {
        const int jl  = jc * 32 + jj;
        const int jq  = sJq[jl];
        const int ipb = sIpB[jl];
#pragma unroll
        for (int u = 0; u < 8; u++) {
            const int c = cb + u * 8;   // c = b*16 + n
            const int b = c >> 4;
            const int n = c & 15;
            float v = sCD[jl][n];
            if (jq >= 0)
                v += __half2float(g_B16[((size_t)n * MROWS + ipb + b) * KLEN + jq]);
            sT[jl][c] = v;
        }
    }
    __syncthreads();

#pragma unroll
    for (int w = 0; w < 4; w++) {
        const int jr = w * 16 + (t >> 4);
        const int c4 = (t & 15) * 4;
        float4 v = make_float4(sT[jr][c4], sT[jr][c4 + 1], sT[jr][c4 + 2], sT[jr][c4 + 3]);
        *(float4*)(out + ((long long)i * KLEN + (j0 + jr)) * 64 + c4) = v;
    }
}

// ---------------- launch ----------------
extern "C" void kernel_launch(void* const* d_in, const int* in_sizes, int n_in,
                              void* d_out, int out_size)
{
    const float* q   = (const float*)d_in[0];
    const float* whk = (const float*)d_in[1];
    const float* r   = (const float*)d_in[2];
    const float* Wr  = (const float*)d_in[3];
    const float* rwb = (const float*)d_in[4];
    const float* rrb = (const float*)d_in[5];
    float* out = (float*)d_out;
    (void)in_sizes; (void)n_in; (void)out_size;

    float *p_rhk4;
    __half *p_Ah, *p_Bh, *p_B16;
    __nv_bfloat16 *p_r3, *p_Wr3;
    cudaGetSymbolAddress((void**)&p_rhk4, g_rhk4);
    cudaGetSymbolAddress((void**)&p_B16,  g_B16);
    cudaGetSymbolAddress((void**)&p_Ah,   g_Ah);
    cudaGetSymbolAddress((void**)&p_Bh,   g_Bh);
    cudaGetSymbolAddress((void**)&p_r3,   g_r3);
    cudaGetSymbolAddress((void**)&p_Wr3,  g_Wr3);

    // conversions
    conv_mat<<<KLEN,   256>>>(r,  p_r3, 0);   // A-side [h|h|l]
    conv_mat<<<DMODEL, 256>>>(Wr, p_Wr3, 1);  // B-side [h|l|h]
    conv_q_h<<<MROWS,  256>>>(q);

    // 1) rhk = r.Wr^T, bf16 triple-split, split-K=4 slabs (M=2048,N=1024,K=768 each)
    gemm_nt_mma<0, 0><<<dim3(DMODEL / 128, KLEN / 128, KSPLIT), 256>>>(
        (const uint16_t*)p_r3, (const uint16_t*)p_Wr3, p_rhk4,
        KSLAB, KBIG3, KBIG3, DMODEL,
        KSLAB, KSLAB, (long long)KLEN * DMODEL);
    reduce4_conv<<<(KLEN * DMODEL) / (256 * 4), 256>>>();

    // 2) C[j,n], D[j,n]
    bias_kernel<<<KLEN, 512>>>(whk, rwb, rrb);

    // 3) B[n][(i,b)][j] fp16 out  (per head: M=4096, N=2048, K=128 fp16 double-split)
    gemm_nt_mma<1, 1><<<dim3(KLEN / 128, MROWS / 128, NHEAD), 256>>>(
        (const uint16_t*)p_Ah, (const uint16_t*)p_Bh, p_B16,
        KH2, KH2, KH2, KLEN,
        (long long)MROWS * KH2, (long long)KLEN * KH2, (long long)MROWS * KLEN);

    // 4) rel-shift gather + bias + transpose
    shuffle_kernel<<<dim3(KLEN / 64, QLEN), 256>>>(out);
}

// round 10
// speedup vs baseline: 2.2514x; 1.1032x over previous
#include <cuda_runtime.h>
#include <cuda_bf16.h>
#include <cuda_fp16.h>
#include <cstdint>

#define QLEN   1024
#define KLEN   2048
#define NHEAD  16
#define DHEAD  64
#define BSZ    4
#define DMODEL 1024
#define MROWS  (QLEN * BSZ)   // 4096 merged (i,b) rows
#define KH2BIG 2048           // 2*DMODEL (fp16 double-split rhk GEMM)
#define KSPLIT 4
#define KSLAB2 (KH2BIG / KSPLIT)  // 512
#define KH2    128            // 2*DHEAD (fp16 double-split gemm-B)

// ---------------- scratch ----------------
__device__ float g_rhk4[(size_t)KSPLIT * KLEN * DMODEL];      // split-K slabs (32MB)
__device__ float g_rhk[KLEN * DMODEL];                        // r_head_k [j][n*64+d]
__device__ __half g_B16[(size_t)NHEAD * MROWS * KLEN];        // B [n][(i,b)][j] fp16 (256MB)
__device__ float g_C[KLEN * NHEAD];
__device__ float g_D[KLEN * NHEAD];
__device__ __half g_Ah[(size_t)NHEAD * MROWS * KH2];          // q fp16:   [n][(i,b)][hi64|lo64]
__device__ __half g_Bh[(size_t)NHEAD * KLEN * KH2];           // rhk fp16: [n][j][hi64|lo64]
__device__ __half g_r2h[(size_t)KLEN * KH2BIG];               // r fp16:   [j][hi1024|lo1024]
__device__ __half g_Wr2h[(size_t)DMODEL * KH2BIG];            // W_r fp16: [nd][hi1024|lo1024]

// ---------------- HMMA NT GEMM (fp16, fp32 acc, ldmatrix frag loads) ----------------
// C[m][n] = sum_k A[m][k]*B[n][k]. CTA 128x128, BK=32, 8 warps of 64x32,
// mma.sync.m16n8k16, double-buffered smem.
#define SPAD 40   // 20-word row stride: conflict-free for ldmatrix (8 rows hit 32 banks)

template<int OUT_HALF>
__global__ __launch_bounds__(256)
void gemm_nt_mma(const uint16_t* __restrict__ A,
                 const uint16_t* __restrict__ Bm,
                 void* __restrict__ CoutV,
                 int K, int lda, int ldb, int ldc,
                 long long sA, long long sB, long long sC)
{
    __shared__ __align__(16) uint16_t As[2][128][SPAD];
    __shared__ __align__(16) uint16_t Bs[2][128][SPAD];

    A  += (long long)blockIdx.z * sA;
    Bm += (long long)blockIdx.z * sB;
    const int m0 = blockIdx.y << 7, n0 = blockIdx.x << 7;

    const int t    = threadIdx.x;
    const int lane = t & 31;
    const int wid  = t >> 5;
    const int wm   = (wid & 1) * 64;
    const int wn   = (wid >> 1) * 32;
    const int nchunk = K >> 5;

    const int srow0 = t >> 2, sc16 = (t & 3) << 3;
    const int srow1 = srow0 + 64;

    const uint16_t* Ab0 = A  + (long long)(m0 + srow0) * lda + sc16;
    const uint16_t* Ab1 = A  + (long long)(m0 + srow1) * lda + sc16;
    const uint16_t* Bb0 = Bm + (long long)(n0 + srow0) * ldb + sc16;
    const uint16_t* Bb1 = Bm + (long long)(n0 + srow1) * ldb + sc16;

    const uint32_t sA_u32 = (uint32_t)__cvta_generic_to_shared(&As[0][0][0]);
    const uint32_t sB_u32 = (uint32_t)__cvta_generic_to_shared(&Bs[0][0][0]);
    // per-lane ldmatrix row/col offsets
    const int arow = lane & 15;                         // A: row within 16
    const int acol = (lane >> 4) << 3;                  // A: +8 for upper half
    const int brow = (lane & 7) + ((lane >> 4) << 3);   // B: row within g-pair
    const int bcol = ((lane >> 3) & 1) << 3;            // B: +8 k offset

    float acc[4][4][4];
#pragma unroll
    for (int f = 0; f < 4; f++)
#pragma unroll
        for (int g = 0; g < 4; g++)
#pragma unroll
            for (int c = 0; c < 4; c++) acc[f][g][c] = 0.f;

    uint4 ra0 = *(const uint4*)Ab0;
    uint4 ra1 = *(const uint4*)Ab1;
    uint4 rb0 = *(const uint4*)Bb0;
    uint4 rb1 = *(const uint4*)Bb1;

    for (int kc = 0; kc < nchunk; kc++) {
        const int buf = kc & 1;
        *(uint4*)&As[buf][srow0][sc16] = ra0;
        *(uint4*)&As[buf][srow1][sc16] = ra1;
        *(uint4*)&Bs[buf][srow0][sc16] = rb0;
        *(uint4*)&Bs[buf][srow1][sc16] = rb1;
        __syncthreads();

        if (kc + 1 < nchunk) {
            const int ko = (kc + 1) << 5;
            ra0 = *(const uint4*)(Ab0 + ko);
            ra1 = *(const uint4*)(Ab1 + ko);
            rb0 = *(const uint4*)(Bb0 + ko);
            rb1 = *(const uint4*)(Bb1 + ko);
        }

        const uint32_t sAb = sA_u32 + (uint32_t)buf * (128 * SPAD * 2);
        const uint32_t sBb = sB_u32 + (uint32_t)buf * (128 * SPAD * 2);

#pragma unroll
        for (int ks = 0; ks < 32; ks += 16) {
            uint32_t af[4][4], bp[2][4];
#pragma unroll
            for (int f = 0; f < 4; f++) {
                uint32_t addr = sAb + (uint32_t)(((wm + f * 16 + arow) * SPAD + ks + acol) * 2);
                asm volatile("ldmatrix.sync.aligned.m8n8.x4.shared.b16 {%0,%1,%2,%3}, [%4];"
                    : "=r"(af[f][0]), "=r"(af[f][1]), "=r"(af[f][2]), "=r"(af[f][3])
                    : "r"(addr));
            }
#pragma unroll
            for (int gp = 0; gp < 2; gp++) {
                uint32_t addr = sBb + (uint32_t)(((wn + gp * 16 + brow) * SPAD + ks + bcol) * 2);
                asm volatile("ldmatrix.sync.aligned.m8n8.x4.shared.b16 {%0,%1,%2,%3}, [%4];"
                    : "=r"(bp[gp][0]), "=r"(bp[gp][1]), "=r"(bp[gp][2]), "=r"(bp[gp][3])
                    : "r"(addr));
            }
#pragma unroll
            for (int f = 0; f < 4; f++)
#pragma unroll
                for (int g = 0; g < 4; g++)
                    asm volatile(
                        "mma.sync.aligned.m16n8k16.row.col.f32.f16.f16.f32 "
                        "{%0,%1,%2,%3}, {%4,%5,%6,%7}, {%8,%9}, {%0,%1,%2,%3};"
                        : "+f"(acc[f][g][0]), "+f"(acc[f][g][1]),
                          "+f"(acc[f][g][2]), "+f"(acc[f][g][3])
                        : "r"(af[f][0]), "r"(af[f][1]), "r"(af[f][2]), "r"(af[f][3]),
                          "r"(bp[g >> 1][(g & 1) * 2]), "r"(bp[g >> 1][(g & 1) * 2 + 1]));
        }
        __syncthreads();
    }

    if (OUT_HALF) {
        __half* Cout = (__half*)CoutV + (long long)blockIdx.z * sC;
#pragma unroll
        for (int f = 0; f < 4; f++) {
            const int r = m0 + wm + f * 16 + (lane >> 2);
#pragma unroll
            for (int g = 0; g < 4; g++) {
                const int c = n0 + wn + g * 8 + ((lane & 3) << 1);
                *(__half2*)(Cout + (long long)r * ldc + c)       = __floats2half2_rn(acc[f][g][0], acc[f][g][1]);
                *(__half2*)(Cout + (long long)(r + 8) * ldc + c) = __floats2half2_rn(acc[f][g][2], acc[f][g][3]);
            }
        }
    } else {
        float* Cout = (float*)CoutV + (long long)blockIdx.z * sC;
#pragma unroll
        for (int f = 0; f < 4; f++) {
            const int r = m0 + wm + f * 16 + (lane >> 2);
#pragma unroll
            for (int g = 0; g < 4; g++) {
                const int c = n0 + wn + g * 8 + ((lane & 3) << 1);
                *(float2*)(Cout + (long long)r * ldc + c)       = make_float2(acc[f][g][0], acc[f][g][1]);
                *(float2*)(Cout + (long long)(r + 8) * ldc + c) = make_float2(acc[f][g][2], acc[f][g][3]);
            }
        }
    }
}

// ---------------- split-K reduce fused with rhk -> fp16 double-split ----------------
__global__ __launch_bounds__(256) void reduce4_conv() {
    const size_t i = ((size_t)blockIdx.x * 256 + threadIdx.x) * 4;
    float4 a = *(const float4*)&g_rhk4[i];
    float4 b = *(const float4*)&g_rhk4[i + (size_t)KLEN * DMODEL];
    float4 c = *(const float4*)&g_rhk4[i + (size_t)2 * KLEN * DMODEL];
    float4 d = *(const float4*)&g_rhk4[i + (size_t)3 * KLEN * DMODEL];
    float4 s = make_float4(a.x + b.x + c.x + d.x, a.y + b.y + c.y + d.y,
                           a.z + b.z + c.z + d.z, a.w + b.w + c.w + d.w);
    *(float4*)&g_rhk[i] = s;

    const int j = (int)(i >> 10);
    const int e = (int)(i & 1023);
    const int n = e >> 6, d0 = e & 63;
    __half* dst = g_Bh + ((size_t)n * KLEN + j) * KH2;
    float v[4] = {s.x, s.y, s.z, s.w};
    __half hi[4], lo[4];
#pragma unroll
    for (int u = 0; u < 4; u++) {
        hi[u] = __float2half_rn(v[u]);
        lo[u] = __float2half_rn(v[u] - __half2float(hi[u]));
    }
    *(__half2*)(dst + d0)          = __halves2half2(hi[0], hi[1]);
    *(__half2*)(dst + d0 + 2)      = __halves2half2(hi[2], hi[3]);
    *(__half2*)(dst + 64 + d0)     = __halves2half2(lo[0], lo[1]);
    *(__half2*)(dst + 64 + d0 + 2) = __halves2half2(lo[2], lo[3]);
}

// ---------------- conversions ----------------
// fp16 double-split of a [rows x 1024] fp32 matrix -> [rows][hi1024|lo1024]
__global__ __launch_bounds__(256) void conv_mat_h(const float* __restrict__ in,
                                                  __half* __restrict__ outp) {
    const int r = blockIdx.x;
#pragma unroll
    for (int it = 0; it < 4; it++) {
        int e = threadIdx.x + it * 256;
        float x = in[(long long)r * 1024 + e];
        __half hi = __float2half_rn(x);
        __half lo = __float2half_rn(x - __half2float(hi));
        __half* dst = outp + (size_t)r * KH2BIG;
        dst[e] = hi;
        dst[1024 + e] = lo;
    }
}
// fp16 double-split of q: [n][(i,b)][hi64|lo64]
__global__ __launch_bounds__(256) void conv_q_h(const float* __restrict__ q) {
    const int r = blockIdx.x;
#pragma unroll
    for (int it = 0; it < 4; it++) {
        int e = threadIdx.x + it * 256;
        int n = e >> 6, d = e & 63;
        float x = q[(long long)r * 1024 + e];
        __half hi = __float2half_rn(x);
        __half lo = __float2half_rn(x - __half2float(hi));
        __half* dst = g_Ah + ((size_t)n * MROWS + r) * KH2;
        dst[d] = hi;
        dst[64 + d] = lo;
    }
}

// ---------------- C[j,n] and D[j,n] bias terms ----------------
__global__ __launch_bounds__(512)
void bias_kernel(const float* __restrict__ whk,
                 const float* __restrict__ rwb,
                 const float* __restrict__ rrb)
{
    const int j = blockIdx.x;
    const int n = threadIdx.x >> 5;
    const int l = threadIdx.x & 31;

    float s = 0.f;
#pragma unroll
    for (int e = l; e < BSZ * DHEAD; e += 32) {
        int b = e >> 6, d = e & 63;
        s += rwb[n * DHEAD + d] * whk[(((j * BSZ + b) * NHEAD) + n) * DHEAD + d];
    }
    float sd = 0.f;
#pragma unroll
    for (int d = l; d < DHEAD; d += 32)
        sd += rrb[n * DHEAD + d] * g_rhk[j * DMODEL + n * DHEAD + d];

#pragma unroll
    for (int o = 16; o > 0; o >>= 1) {
        s  += __shfl_xor_sync(0xffffffffu, s,  o);
        sd += __shfl_xor_sync(0xffffffffu, sd, o);
    }
    if (l == 0) {
        g_C[j * NHEAD + n] = s;
        g_D[j * NHEAD + n] = sd;
    }
}

// ---------------- rel_shift gather + bias add + (b,n) transpose ----------------
__global__ __launch_bounds__(256)
void shuffle_kernel(float* __restrict__ out)
{
    __shared__ float sT[64][65];
    __shared__ float sCD[64][17];
    __shared__ int   sIpB[64];
    __shared__ int   sJq[64];

    const int t  = threadIdx.x;
    const int i  = blockIdx.y;
    const int j0 = blockIdx.x * 64;

    for (int idx = t; idx < 64 * NHEAD; idx += 256) {
        const int jl = idx >> 4;
        const int n  = idx & 15;
        const int j  = j0 + jl;
        const int pos = i * KLEN + j + QLEN;
        const int ip  = pos / (KLEN + 1);
        const int jp  = pos - ip * (KLEN + 1);
        float v = g_C[j * NHEAD + n];
        if (jp != 0) v += g_D[(jp - 1) * NHEAD + n];
        sCD[jl][n] = v;
        if (n == 0) { sIpB[jl] = ip * BSZ; sJq[jl] = jp - 1; }
    }
    __syncthreads();

    const int jj = t & 31;
    const int cb = t >> 5;

#pragma unroll
    for (int jc = 0; jc < 2; jc++) {
        const int jl  = jc * 32 + jj;
        const int jq  = sJq[jl];
        const int ipb = sIpB[jl];
#pragma unroll
        for (int u = 0; u < 8; u++) {
            const int c = cb + u * 8;   // c = b*16 + n
            const int b = c >> 4;
            const int n = c & 15;
            float v = sCD[jl][n];
            if (jq >= 0)
                v += __half2float(g_B16[((size_t)n * MROWS + ipb + b) * KLEN + jq]);
            sT[jl][c] = v;
        }
    }
    __syncthreads();

#pragma unroll
    for (int w = 0; w < 4; w++) {
        const int jr = w * 16 + (t >> 4);
        const int c4 = (t & 15) * 4;
        float4 v = make_float4(sT[jr][c4], sT[jr][c4 + 1], sT[jr][c4 + 2], sT[jr][c4 + 3]);
        *(float4*)(out + ((long long)i * KLEN + (j0 + jr)) * 64 + c4) = v;
    }
}

// ---------------- launch ----------------
extern "C" void kernel_launch(void* const* d_in, const int* in_sizes, int n_in,
                              void* d_out, int out_size)
{
    const float* q   = (const float*)d_in[0];
    const float* whk = (const float*)d_in[1];
    const float* r   = (const float*)d_in[2];
    const float* Wr  = (const float*)d_in[3];
    const float* rwb = (const float*)d_in[4];
    const float* rrb = (const float*)d_in[5];
    float* out = (float*)d_out;
    (void)in_sizes; (void)n_in; (void)out_size;

    float *p_rhk4;
    __half *p_Ah, *p_Bh, *p_B16, *p_r2h, *p_Wr2h;
    cudaGetSymbolAddress((void**)&p_rhk4, g_rhk4);
    cudaGetSymbolAddress((void**)&p_B16,  g_B16);
    cudaGetSymbolAddress((void**)&p_Ah,   g_Ah);
    cudaGetSymbolAddress((void**)&p_Bh,   g_Bh);
    cudaGetSymbolAddress((void**)&p_r2h,  g_r2h);
    cudaGetSymbolAddress((void**)&p_Wr2h, g_Wr2h);

    // conversions (fp16 double-split everywhere)
    conv_mat_h<<<KLEN,   256>>>(r,  p_r2h);
    conv_mat_h<<<DMODEL, 256>>>(Wr, p_Wr2h);
    conv_q_h  <<<MROWS,  256>>>(q);

    // 1) rhk = r.Wr^T, fp16 double-split, split-K=4 (M=2048,N=1024,K=512 each)
    gemm_nt_mma<0><<<dim3(DMODEL / 128, KLEN / 128, KSPLIT), 256>>>(
        (const uint16_t*)p_r2h, (const uint16_t*)p_Wr2h, p_rhk4,
        KSLAB2, KH2BIG, KH2BIG, DMODEL,
        KSLAB2, KSLAB2, (long long)KLEN * DMODEL);
    reduce4_conv<<<(KLEN * DMODEL) / (256 * 4), 256>>>();

    // 2) C[j,n], D[j,n]
    bias_kernel<<<KLEN, 512>>>(whk, rwb, rrb);

    // 3) B[n][(i,b)][j] fp16 out  (per head: M=4096, N=2048, K=128)
    gemm_nt_mma<1><<<dim3(KLEN / 128, MROWS / 128, NHEAD), 256>>>(
        (const uint16_t*)p_Ah, (const uint16_t*)p_Bh, p_B16,
        KH2, KH2, KH2, KLEN,
        (long long)MROWS * KH2, (long long)KLEN * KH2, (long long)MROWS * KLEN);

    // 4) rel-shift gather + bias + transpose
    shuffle_kernel<<<dim3(KLEN / 64, QLEN), 256>>>(out);
}

// round 11
// speedup vs baseline: 2.4643x; 1.0946x over previous
#include <cuda_runtime.h>
#include <cuda_bf16.h>
#include <cuda_fp16.h>
#include <cstdint>

#define QLEN   1024
#define KLEN   2048
#define NHEAD  16
#define DHEAD  64
#define BSZ    4
#define DMODEL 1024
#define MROWS  (QLEN * BSZ)   // 4096 merged (i,b) rows
#define KH2BIG 2048           // 2*DMODEL (fp16 double-split rhk GEMM)
#define KSPLIT 4
#define KSLAB2 (KH2BIG / KSPLIT)  // 512
#define KH2    128            // 2*DHEAD (fp16 double-split gemm-B)

// ---------------- scratch ----------------
__device__ float g_rhk4[(size_t)KSPLIT * KLEN * DMODEL];      // split-K slabs (32MB)
__device__ float g_rhk[KLEN * DMODEL];                        // r_head_k [j][n*64+d]
__device__ __half g_B16[(size_t)NHEAD * MROWS * KLEN];        // B [n][(i,b)][j] fp16 (256MB)
__device__ float g_C[KLEN * NHEAD];
__device__ float g_D[KLEN * NHEAD];
__device__ __half g_Ah[(size_t)NHEAD * MROWS * KH2];          // q fp16:   [n][(i,b)][hi64|lo64]
__device__ __half g_Bh[(size_t)NHEAD * KLEN * KH2];           // rhk fp16: [n][j][hi64|lo64]
__device__ __half g_r2h[(size_t)KLEN * KH2BIG];               // r fp16:   [j][hi1024|lo1024]
__device__ __half g_Wr2h[(size_t)DMODEL * KH2BIG];            // W_r fp16: [nd][hi1024|lo1024]

__device__ __forceinline__ void cp_async16(uint32_t smem, const void* gptr) {
    asm volatile("cp.async.ca.shared.global [%0], [%1], 16;" :: "r"(smem), "l"(gptr));
}

// ================= gemm-B: single-shot K=128 (fp16 in, fp16 out) =================
// C[m][j] = sum_k A[m][k]*B[j][k], per-head. CTA 128x128, full K in smem,
// cp.async bulk load -> one sync -> 8 ks-steps of ldmatrix+mma -> half2 stores.
#define SPB 136   // smem row stride fp16: 68 words -> ldmatrix conflict-free
#define GB_SMEM (2 * 128 * SPB * 2)   // 69632 B

__global__ __launch_bounds__(256)
void gemm_b128(const __half* __restrict__ Ag, const __half* __restrict__ Bg,
               __half* __restrict__ Cg)
{
    extern __shared__ __align__(16) uint16_t sm[];
    uint16_t* As = sm;
    uint16_t* Bs = sm + 128 * SPB;

    const int head = blockIdx.z;
    const __half* A = Ag + (size_t)head * MROWS * KH2 + (blockIdx.y << 7) * KH2;
    const __half* B = Bg + (size_t)head * KLEN  * KH2 + (blockIdx.x << 7) * KH2;
    __half* Cout = Cg + (size_t)head * MROWS * KLEN
                      + (size_t)(blockIdx.y << 7) * KLEN + (blockIdx.x << 7);

    const int t    = threadIdx.x;
    const int lane = t & 31;
    const int wid  = t >> 5;
    const int wm   = (wid & 1) * 64;
    const int wn   = (wid >> 1) * 32;

    const uint32_t sA_u32 = (uint32_t)__cvta_generic_to_shared(As);
    const uint32_t sB_u32 = (uint32_t)__cvta_generic_to_shared(Bs);

    // bulk load: 2048 uint4 per tile / 256 threads = 8 each
#pragma unroll
    for (int u = 0; u < 8; u++) {
        int idx = t + u * 256;
        int row = idx >> 4, c8 = (idx & 15) << 3;
        cp_async16(sA_u32 + (uint32_t)(row * SPB + c8) * 2, A + (size_t)row * KH2 + c8);
    }
#pragma unroll
    for (int u = 0; u < 8; u++) {
        int idx = t + u * 256;
        int row = idx >> 4, c8 = (idx & 15) << 3;
        cp_async16(sB_u32 + (uint32_t)(row * SPB + c8) * 2, B + (size_t)row * KH2 + c8);
    }
    asm volatile("cp.async.commit_group;");

    const int arow = lane & 15;
    const int acol = (lane >> 4) << 3;
    const int brow = (lane & 7) + ((lane >> 4) << 3);
    const int bcol = ((lane >> 3) & 1) << 3;

    float acc[4][4][4];
#pragma unroll
    for (int f = 0; f < 4; f++)
#pragma unroll
        for (int g = 0; g < 4; g++)
#pragma unroll
            for (int c = 0; c < 4; c++) acc[f][g][c] = 0.f;

    asm volatile("cp.async.wait_group 0;");
    __syncthreads();

#pragma unroll
    for (int ks = 0; ks < 128; ks += 16) {
        uint32_t af[4][4], bp[2][4];
#pragma unroll
        for (int f = 0; f < 4; f++) {
            uint32_t addr = sA_u32 + (uint32_t)(((wm + f * 16 + arow) * SPB + ks + acol) * 2);
            asm volatile("ldmatrix.sync.aligned.m8n8.x4.shared.b16 {%0,%1,%2,%3}, [%4];"
                : "=r"(af[f][0]), "=r"(af[f][1]), "=r"(af[f][2]), "=r"(af[f][3])
                : "r"(addr));
        }
#pragma unroll
        for (int gp = 0; gp < 2; gp++) {
            uint32_t addr = sB_u32 + (uint32_t)(((wn + gp * 16 + brow) * SPB + ks + bcol) * 2);
            asm volatile("ldmatrix.sync.aligned.m8n8.x4.shared.b16 {%0,%1,%2,%3}, [%4];"
                : "=r"(bp[gp][0]), "=r"(bp[gp][1]), "=r"(bp[gp][2]), "=r"(bp[gp][3])
                : "r"(addr));
        }
#pragma unroll
        for (int f = 0; f < 4; f++)
#pragma unroll
            for (int g = 0; g < 4; g++)
                asm volatile(
                    "mma.sync.aligned.m16n8k16.row.col.f32.f16.f16.f32 "
                    "{%0,%1,%2,%3}, {%4,%5,%6,%7}, {%8,%9}, {%0,%1,%2,%3};"
                    : "+f"(acc[f][g][0]), "+f"(acc[f][g][1]),
                      "+f"(acc[f][g][2]), "+f"(acc[f][g][3])
                    : "r"(af[f][0]), "r"(af[f][1]), "r"(af[f][2]), "r"(af[f][3]),
                      "r"(bp[g >> 1][(g & 1) * 2]), "r"(bp[g >> 1][(g & 1) * 2 + 1]));
    }

#pragma unroll
    for (int f = 0; f < 4; f++) {
        const int r = wm + f * 16 + (lane >> 2);
#pragma unroll
        for (int g = 0; g < 4; g++) {
            const int c = wn + g * 8 + ((lane & 3) << 1);
            *(__half2*)(Cout + (size_t)r * KLEN + c)       = __floats2half2_rn(acc[f][g][0], acc[f][g][1]);
            *(__half2*)(Cout + (size_t)(r + 8) * KLEN + c) = __floats2half2_rn(acc[f][g][2], acc[f][g][3]);
        }
    }
}

// ================= rhk GEMM: 3-stage cp.async pipeline, BK=32 =================
#define SPAD 40
#define STAGE_U16 (128 * SPAD)                 // per tile per stage (uint16)
#define RHK_SMEM  (6 * STAGE_U16 * 2)          // 61440 B

__global__ __launch_bounds__(256)
void gemm_rhk(const __half* __restrict__ Ag, const __half* __restrict__ Bg,
              float* __restrict__ Cg)
{
    extern __shared__ __align__(16) uint16_t sm[];

    const __half* A = Ag + (long long)blockIdx.z * KSLAB2 + (blockIdx.y << 7) * KH2BIG;
    const __half* B = Bg + (long long)blockIdx.z * KSLAB2 + (blockIdx.x << 7) * KH2BIG;
    float* Cout = Cg + (long long)blockIdx.z * KLEN * DMODEL
                     + (long long)(blockIdx.y << 7) * DMODEL + (blockIdx.x << 7);

    const int t    = threadIdx.x;
    const int lane = t & 31;
    const int wid  = t >> 5;
    const int wm   = (wid & 1) * 64;
    const int wn   = (wid >> 1) * 32;
    const int nchunk = KSLAB2 / 32;   // 16

    const uint32_t s_u32 = (uint32_t)__cvta_generic_to_shared(sm);

    // per-chunk staging: 512 uint4 per tile / 256 threads = 2 each
    const int srow = t >> 2, sc8 = (t & 3) << 3;

    auto issue = [&](int kc) {
        const int st = kc % 3;
        const uint32_t sA = s_u32 + (uint32_t)(st * STAGE_U16) * 2;
        const uint32_t sB = s_u32 + (uint32_t)((3 + st) * STAGE_U16) * 2;
        const int ko = kc << 5;
#pragma unroll
        for (int u = 0; u < 2; u++) {
            int row = srow + u * 64;
            cp_async16(sA + (uint32_t)(row * SPAD + sc8) * 2, A + (long long)row * KH2BIG + ko + sc8);
            cp_async16(sB + (uint32_t)(row * SPAD + sc8) * 2, B + (long long)row * KH2BIG + ko + sc8);
        }
    };

    const int arow = lane & 15;
    const int acol = (lane >> 4) << 3;
    const int brow = (lane & 7) + ((lane >> 4) << 3);
    const int bcol = ((lane >> 3) & 1) << 3;

    float acc[4][4][4];
#pragma unroll
    for (int f = 0; f < 4; f++)
#pragma unroll
        for (int g = 0; g < 4; g++)
#pragma unroll
            for (int c = 0; c < 4; c++) acc[f][g][c] = 0.f;

    issue(0); asm volatile("cp.async.commit_group;");
    issue(1); asm volatile("cp.async.commit_group;");

    for (int kc = 0; kc < nchunk; kc++) {
        asm volatile("cp.async.wait_group 1;");
        __syncthreads();

        const int st = kc % 3;
        const uint32_t sA = s_u32 + (uint32_t)(st * STAGE_U16) * 2;
        const uint32_t sB = s_u32 + (uint32_t)((3 + st) * STAGE_U16) * 2;

#pragma unroll
        for (int ks = 0; ks < 32; ks += 16) {
            uint32_t af[4][4], bp[2][4];
#pragma unroll
            for (int f = 0; f < 4; f++) {
                uint32_t addr = sA + (uint32_t)(((wm + f * 16 + arow) * SPAD + ks + acol) * 2);
                asm volatile("ldmatrix.sync.aligned.m8n8.x4.shared.b16 {%0,%1,%2,%3}, [%4];"
                    : "=r"(af[f][0]), "=r"(af[f][1]), "=r"(af[f][2]), "=r"(af[f][3])
                    : "r"(addr));
            }
#pragma unroll
            for (int gp = 0; gp < 2; gp++) {
                uint32_t addr = sB + (uint32_t)(((wn + gp * 16 + brow) * SPAD + ks + bcol) * 2);
                asm volatile("ldmatrix.sync.aligned.m8n8.x4.shared.b16 {%0,%1,%2,%3}, [%4];"
                    : "=r"(bp[gp][0]), "=r"(bp[gp][1]), "=r"(bp[gp][2]), "=r"(bp[gp][3])
                    : "r"(addr));
            }
#pragma unroll
            for (int f = 0; f < 4; f++)
#pragma unroll
                for (int g = 0; g < 4; g++)
                    asm volatile(
                        "mma.sync.aligned.m16n8k16.row.col.f32.f16.f16.f32 "
                        "{%0,%1,%2,%3}, {%4,%5,%6,%7}, {%8,%9}, {%0,%1,%2,%3};"
                        : "+f"(acc[f][g][0]), "+f"(acc[f][g][1]),
                          "+f"(acc[f][g][2]), "+f"(acc[f][g][3])
                        : "r"(af[f][0]), "r"(af[f][1]), "r"(af[f][2]), "r"(af[f][3]),
                          "r"(bp[g >> 1][(g & 1) * 2]), "r"(bp[g >> 1][(g & 1) * 2 + 1]));
        }
        __syncthreads();
        if (kc + 2 < nchunk) issue(kc + 2);
        asm volatile("cp.async.commit_group;");
    }

#pragma unroll
    for (int f = 0; f < 4; f++) {
        const int r = wm + f * 16 + (lane >> 2);
#pragma unroll
        for (int g = 0; g < 4; g++) {
            const int c = wn + g * 8 + ((lane & 3) << 1);
            *(float2*)(Cout + (long long)r * DMODEL + c)       = make_float2(acc[f][g][0], acc[f][g][1]);
            *(float2*)(Cout + (long long)(r + 8) * DMODEL + c) = make_float2(acc[f][g][2], acc[f][g][3]);
        }
    }
}

// ---------------- split-K reduce fused with rhk -> fp16 double-split ----------------
__global__ __launch_bounds__(256) void reduce4_conv() {
    const size_t i = ((size_t)blockIdx.x * 256 + threadIdx.x) * 4;
    float4 a = *(const float4*)&g_rhk4[i];
    float4 b = *(const float4*)&g_rhk4[i + (size_t)KLEN * DMODEL];
    float4 c = *(const float4*)&g_rhk4[i + (size_t)2 * KLEN * DMODEL];
    float4 d = *(const float4*)&g_rhk4[i + (size_t)3 * KLEN * DMODEL];
    float4 s = make_float4(a.x + b.x + c.x + d.x, a.y + b.y + c.y + d.y,
                           a.z + b.z + c.z + d.z, a.w + b.w + c.w + d.w);
    *(float4*)&g_rhk[i] = s;

    const int j = (int)(i >> 10);
    const int e = (int)(i & 1023);
    const int n = e >> 6, d0 = e & 63;
    __half* dst = g_Bh + ((size_t)n * KLEN + j) * KH2;
    float v[4] = {s.x, s.y, s.z, s.w};
    __half hi[4], lo[4];
#pragma unroll
    for (int u = 0; u < 4; u++) {
        hi[u] = __float2half_rn(v[u]);
        lo[u] = __float2half_rn(v[u] - __half2float(hi[u]));
    }
    *(__half2*)(dst + d0)          = __halves2half2(hi[0], hi[1]);
    *(__half2*)(dst + d0 + 2)      = __halves2half2(hi[2], hi[3]);
    *(__half2*)(dst + 64 + d0)     = __halves2half2(lo[0], lo[1]);
    *(__half2*)(dst + 64 + d0 + 2) = __halves2half2(lo[2], lo[3]);
}

// ---------------- conversions ----------------
__global__ __launch_bounds__(256) void conv_mat_h(const float* __restrict__ in,
                                                  __half* __restrict__ outp) {
    const int r = blockIdx.x;
#pragma unroll
    for (int it = 0; it < 4; it++) {
        int e = threadIdx.x + it * 256;
        float x = in[(long long)r * 1024 + e];
        __half hi = __float2half_rn(x);
        __half lo = __float2half_rn(x - __half2float(hi));
        __half* dst = outp + (size_t)r * KH2BIG;
        dst[e] = hi;
        dst[1024 + e] = lo;
    }
}
__global__ __launch_bounds__(256) void conv_q_h(const float* __restrict__ q) {
    const int r = blockIdx.x;
#pragma unroll
    for (int it = 0; it < 4; it++) {
        int e = threadIdx.x + it * 256;
        int n = e >> 6, d = e & 63;
        float x = q[(long long)r * 1024 + e];
        __half hi = __float2half_rn(x);
        __half lo = __float2half_rn(x - __half2float(hi));
        __half* dst = g_Ah + ((size_t)n * MROWS + r) * KH2;
        dst[d] = hi;
        dst[64 + d] = lo;
    }
}

// ---------------- C[j,n] and D[j,n] bias terms ----------------
__global__ __launch_bounds__(512)
void bias_kernel(const float* __restrict__ whk,
                 const float* __restrict__ rwb,
                 const float* __restrict__ rrb)
{
    const int j = blockIdx.x;
    const int n = threadIdx.x >> 5;
    const int l = threadIdx.x & 31;

    float s = 0.f;
#pragma unroll
    for (int e = l; e < BSZ * DHEAD; e += 32) {
        int b = e >> 6, d = e & 63;
        s += rwb[n * DHEAD + d] * whk[(((j * BSZ + b) * NHEAD) + n) * DHEAD + d];
    }
    float sd = 0.f;
#pragma unroll
    for (int d = l; d < DHEAD; d += 32)
        sd += rrb[n * DHEAD + d] * g_rhk[j * DMODEL + n * DHEAD + d];

#pragma unroll
    for (int o = 16; o > 0; o >>= 1) {
        s  += __shfl_xor_sync(0xffffffffu, s,  o);
        sd += __shfl_xor_sync(0xffffffffu, sd, o);
    }
    if (l == 0) {
        g_C[j * NHEAD + n] = s;
        g_D[j * NHEAD + n] = sd;
    }
}

// ---------------- rel_shift gather + bias add + (b,n) transpose ----------------
__global__ __launch_bounds__(256)
void shuffle_kernel(float* __restrict__ out)
{
    __shared__ float sT[64][65];
    __shared__ float sCD[64][17];
    __shared__ int   sIpB[64];
    __shared__ int   sJq[64];

    const int t  = threadIdx.x;
    const int i  = blockIdx.y;
    const int j0 = blockIdx.x * 64;

    for (int idx = t; idx < 64 * NHEAD; idx += 256) {
        const int jl = idx >> 4;
        const int n  = idx & 15;
        const int j  = j0 + jl;
        const int pos = i * KLEN + j + QLEN;
        const int ip  = pos / (KLEN + 1);
        const int jp  = pos - ip * (KLEN + 1);
        float v = g_C[j * NHEAD + n];
        if (jp != 0) v += g_D[(jp - 1) * NHEAD + n];
        sCD[jl][n] = v;
        if (n == 0) { sIpB[jl] = ip * BSZ; sJq[jl] = jp - 1; }
    }
    __syncthreads();

    const int jj = t & 31;
    const int cb = t >> 5;

#pragma unroll
    for (int jc = 0; jc < 2; jc++) {
        const int jl  = jc * 32 + jj;
        const int jq  = sJq[jl];
        const int ipb = sIpB[jl];
#pragma unroll
        for (int u = 0; u < 8; u++) {
            const int c = cb + u * 8;   // c = b*16 + n
            const int b = c >> 4;
            const int n = c & 15;
            float v = sCD[jl][n];
            if (jq >= 0)
                v += __half2float(g_B16[((size_t)n * MROWS + ipb + b) * KLEN + jq]);
            sT[jl][c] = v;
        }
    }
    __syncthreads();

#pragma unroll
    for (int w = 0; w < 4; w++) {
        const int jr = w * 16 + (t >> 4);
        const int c4 = (t & 15) * 4;
        float4 v = make_float4(sT[jr][c4], sT[jr][c4 + 1], sT[jr][c4 + 2], sT[jr][c4 + 3]);
        *(float4*)(out + ((long long)i * KLEN + (j0 + jr)) * 64 + c4) = v;
    }
}

// ---------------- launch ----------------
extern "C" void kernel_launch(void* const* d_in, const int* in_sizes, int n_in,
                              void* d_out, int out_size)
{
    const float* q   = (const float*)d_in[0];
    const float* whk = (const float*)d_in[1];
    const float* r   = (const float*)d_in[2];
    const float* Wr  = (const float*)d_in[3];
    const float* rwb = (const float*)d_in[4];
    const float* rrb = (const float*)d_in[5];
    float* out = (float*)d_out;
    (void)in_sizes; (void)n_in; (void)out_size;

    float *p_rhk4;
    __half *p_Ah, *p_Bh, *p_B16, *p_r2h, *p_Wr2h;
    cudaGetSymbolAddress((void**)&p_rhk4, g_rhk4);
    cudaGetSymbolAddress((void**)&p_B16,  g_B16);
    cudaGetSymbolAddress((void**)&p_Ah,   g_Ah);
    cudaGetSymbolAddress((void**)&p_Bh,   g_Bh);
    cudaGetSymbolAddress((void**)&p_r2h,  g_r2h);
    cudaGetSymbolAddress((void**)&p_Wr2h, g_Wr2h);

    cudaFuncSetAttribute(gemm_b128, cudaFuncAttributeMaxDynamicSharedMemorySize, GB_SMEM);
    cudaFuncSetAttribute(gemm_rhk,  cudaFuncAttributeMaxDynamicSharedMemorySize, RHK_SMEM);

    // conversions (fp16 double-split everywhere)
    conv_mat_h<<<KLEN,   256>>>(r,  p_r2h);
    conv_mat_h<<<DMODEL, 256>>>(Wr, p_Wr2h);
    conv_q_h  <<<MROWS,  256>>>(q);

    // 1) rhk = r.Wr^T, fp16 double-split, split-K=4 (M=2048,N=1024,K=512 each)
    gemm_rhk<<<dim3(DMODEL / 128, KLEN / 128, KSPLIT), 256, RHK_SMEM>>>(
        p_r2h, p_Wr2h, p_rhk4);
    reduce4_conv<<<(KLEN * DMODEL) / (256 * 4), 256>>>();

    // 2) C[j,n], D[j,n]
    bias_kernel<<<KLEN, 512>>>(whk, rwb, rrb);

    // 3) B[n][(i,b)][j] fp16 out  (per head: M=4096, N=2048, K=128)
    gemm_b128<<<dim3(KLEN / 128, MROWS / 128, NHEAD), 256, GB_SMEM>>>(
        p_Ah, p_Bh, p_B16);

    // 4) rel-shift gather + bias + transpose
    shuffle_kernel<<<dim3(KLEN / 64, QLEN), 256>>>(out);
}

// round 12
// speedup vs baseline: 2.4680x; 1.0015x over previous
#include <cuda_runtime.h>
#include <cuda_bf16.h>
#include <cuda_fp16.h>
#include <cstdint>

#define QLEN   1024
#define KLEN   2048
#define NHEAD  16
#define DHEAD  64
#define BSZ    4
#define DMODEL 1024
#define MROWS  (QLEN * BSZ)   // 4096 merged (i,b) rows
#define KH2BIG 2048           // 2*DMODEL (fp16 double-split rhk GEMM)
#define KSPLIT 4
#define KSLAB2 (KH2BIG / KSPLIT)  // 512
#define KH2    128            // 2*DHEAD (fp16 double-split gemm-B)

// ---------------- scratch ----------------
__device__ float g_rhk4[(size_t)KSPLIT * KLEN * DMODEL];      // split-K slabs (32MB)
__device__ float g_rhk[KLEN * DMODEL];                        // r_head_k [j][n*64+d]
__device__ __half g_B16[(size_t)NHEAD * MROWS * KLEN];        // B [n][(i,b)][j] fp16 (256MB)
__device__ float g_C[KLEN * NHEAD];
__device__ float g_D[KLEN * NHEAD];
__device__ __half g_Ah[(size_t)NHEAD * MROWS * KH2];          // q fp16:   [n][(i,b)][hi64|lo64]
__device__ __half g_Bh[(size_t)NHEAD * KLEN * KH2];           // rhk fp16: [n][j][hi64|lo64]
__device__ __half g_r2h[(size_t)KLEN * KH2BIG];               // r fp16:   [j][hi1024|lo1024]
__device__ __half g_Wr2h[(size_t)DMODEL * KH2BIG];            // W_r fp16: [nd][hi1024|lo1024]

__device__ __forceinline__ void cp_async16(uint32_t smem, const void* gptr) {
    asm volatile("cp.async.ca.shared.global [%0], [%1], 16;" :: "r"(smem), "l"(gptr));
}

// ================= gemm-B: K=128, two-phase cp.async overlap =================
// C[m][j] = sum_k A[m][k]*B[j][k], per-head. CTA 128x128; K halves loaded as two
// cp.async groups so the first 4 ks-steps overlap the second half's fetch.
#define SPB 136   // smem row stride fp16 (68 words): ldmatrix conflict-free
#define GB_SMEM (2 * 128 * SPB * 2)   // 69632 B

__global__ __launch_bounds__(256)
void gemm_b128(const __half* __restrict__ Ag, const __half* __restrict__ Bg,
               __half* __restrict__ Cg)
{
    extern __shared__ __align__(16) uint16_t sm[];
    uint16_t* As = sm;
    uint16_t* Bs = sm + 128 * SPB;

    const int head = blockIdx.z;
    const __half* A = Ag + (size_t)head * MROWS * KH2 + (blockIdx.y << 7) * KH2;
    const __half* B = Bg + (size_t)head * KLEN  * KH2 + (blockIdx.x << 7) * KH2;
    __half* Cout = Cg + (size_t)head * MROWS * KLEN
                      + (size_t)(blockIdx.y << 7) * KLEN + (blockIdx.x << 7);

    const int t    = threadIdx.x;
    const int lane = t & 31;
    const int wid  = t >> 5;
    const int wm   = (wid & 1) * 64;
    const int wn   = (wid >> 1) * 32;

    const uint32_t sA_u32 = (uint32_t)__cvta_generic_to_shared(As);
    const uint32_t sB_u32 = (uint32_t)__cvta_generic_to_shared(Bs);

    // group 0: K cols [0,64). Each thread: 4 A + 4 B chunks (rows t>>3 + u*32, col (t&7)*8)
    const int lrow = t >> 3;
    const int lc8  = (t & 7) << 3;
#pragma unroll
    for (int u = 0; u < 4; u++) {
        int row = lrow + u * 32;
        cp_async16(sA_u32 + (uint32_t)(row * SPB + lc8) * 2, A + (size_t)row * KH2 + lc8);
        cp_async16(sB_u32 + (uint32_t)(row * SPB + lc8) * 2, B + (size_t)row * KH2 + lc8);
    }
    asm volatile("cp.async.commit_group;");
    // group 1: K cols [64,128)
#pragma unroll
    for (int u = 0; u < 4; u++) {
        int row = lrow + u * 32;
        int c8  = 64 + lc8;
        cp_async16(sA_u32 + (uint32_t)(row * SPB + c8) * 2, A + (size_t)row * KH2 + c8);
        cp_async16(sB_u32 + (uint32_t)(row * SPB + c8) * 2, B + (size_t)row * KH2 + c8);
    }
    asm volatile("cp.async.commit_group;");

    const int arow = lane & 15;
    const int acol = (lane >> 4) << 3;
    const int brow = (lane & 7) + ((lane >> 4) << 3);
    const int bcol = ((lane >> 3) & 1) << 3;

    float acc[4][4][4];
#pragma unroll
    for (int f = 0; f < 4; f++)
#pragma unroll
        for (int g = 0; g < 4; g++)
#pragma unroll
            for (int c = 0; c < 4; c++) acc[f][g][c] = 0.f;

    auto ks_step = [&](int ks) {
        uint32_t af[4][4], bp[2][4];
#pragma unroll
        for (int f = 0; f < 4; f++) {
            uint32_t addr = sA_u32 + (uint32_t)(((wm + f * 16 + arow) * SPB + ks + acol) * 2);
            asm volatile("ldmatrix.sync.aligned.m8n8.x4.shared.b16 {%0,%1,%2,%3}, [%4];"
                : "=r"(af[f][0]), "=r"(af[f][1]), "=r"(af[f][2]), "=r"(af[f][3])
                : "r"(addr));
        }
#pragma unroll
        for (int gp = 0; gp < 2; gp++) {
            uint32_t addr = sB_u32 + (uint32_t)(((wn + gp * 16 + brow) * SPB + ks + bcol) * 2);
            asm volatile("ldmatrix.sync.aligned.m8n8.x4.shared.b16 {%0,%1,%2,%3}, [%4];"
                : "=r"(bp[gp][0]), "=r"(bp[gp][1]), "=r"(bp[gp][2]), "=r"(bp[gp][3])
                : "r"(addr));
        }
#pragma unroll
        for (int f = 0; f < 4; f++)
#pragma unroll
            for (int g = 0; g < 4; g++)
                asm volatile(
                    "mma.sync.aligned.m16n8k16.row.col.f32.f16.f16.f32 "
                    "{%0,%1,%2,%3}, {%4,%5,%6,%7}, {%8,%9}, {%0,%1,%2,%3};"
                    : "+f"(acc[f][g][0]), "+f"(acc[f][g][1]),
                      "+f"(acc[f][g][2]), "+f"(acc[f][g][3])
                    : "r"(af[f][0]), "r"(af[f][1]), "r"(af[f][2]), "r"(af[f][3]),
                      "r"(bp[g >> 1][(g & 1) * 2]), "r"(bp[g >> 1][(g & 1) * 2 + 1]));
    };

    asm volatile("cp.async.wait_group 1;");
    __syncthreads();
#pragma unroll
    for (int ks = 0; ks < 64; ks += 16) ks_step(ks);

    asm volatile("cp.async.wait_group 0;");
    __syncthreads();
#pragma unroll
    for (int ks = 64; ks < 128; ks += 16) ks_step(ks);

#pragma unroll
    for (int f = 0; f < 4; f++) {
        const int r = wm + f * 16 + (lane >> 2);
#pragma unroll
        for (int g = 0; g < 4; g++) {
            const int c = wn + g * 8 + ((lane & 3) << 1);
            *(__half2*)(Cout + (size_t)r * KLEN + c)       = __floats2half2_rn(acc[f][g][0], acc[f][g][1]);
            *(__half2*)(Cout + (size_t)(r + 8) * KLEN + c) = __floats2half2_rn(acc[f][g][2], acc[f][g][3]);
        }
    }
}

// ================= rhk GEMM: 4-stage cp.async pipeline, BK=32 =================
#define SPAD 40
#define STAGE_U16 (128 * SPAD)                 // per tile per stage (uint16)
#define NSTAGE 4
#define RHK_SMEM  (2 * NSTAGE * STAGE_U16 * 2) // 81920 B

__global__ __launch_bounds__(256)
void gemm_rhk(const __half* __restrict__ Ag, const __half* __restrict__ Bg,
              float* __restrict__ Cg)
{
    extern __shared__ __align__(16) uint16_t sm[];

    const __half* A = Ag + (long long)blockIdx.z * KSLAB2 + (blockIdx.y << 7) * KH2BIG;
    const __half* B = Bg + (long long)blockIdx.z * KSLAB2 + (blockIdx.x << 7) * KH2BIG;
    float* Cout = Cg + (long long)blockIdx.z * KLEN * DMODEL
                     + (long long)(blockIdx.y << 7) * DMODEL + (blockIdx.x << 7);

    const int t    = threadIdx.x;
    const int lane = t & 31;
    const int wid  = t >> 5;
    const int wm   = (wid & 1) * 64;
    const int wn   = (wid >> 1) * 32;
    const int nchunk = KSLAB2 / 32;   // 16

    const uint32_t s_u32 = (uint32_t)__cvta_generic_to_shared(sm);
    const int srow = t >> 2, sc8 = (t & 3) << 3;

    auto issue = [&](int kc) {
        const int st = kc % NSTAGE;
        const uint32_t sA = s_u32 + (uint32_t)(st * STAGE_U16) * 2;
        const uint32_t sB = s_u32 + (uint32_t)((NSTAGE + st) * STAGE_U16) * 2;
        const int ko = kc << 5;
#pragma unroll
        for (int u = 0; u < 2; u++) {
            int row = srow + u * 64;
            cp_async16(sA + (uint32_t)(row * SPAD + sc8) * 2, A + (long long)row * KH2BIG + ko + sc8);
            cp_async16(sB + (uint32_t)(row * SPAD + sc8) * 2, B + (long long)row * KH2BIG + ko + sc8);
        }
    };

    const int arow = lane & 15;
    const int acol = (lane >> 4) << 3;
    const int brow = (lane & 7) + ((lane >> 4) << 3);
    const int bcol = ((lane >> 3) & 1) << 3;

    float acc[4][4][4];
#pragma unroll
    for (int f = 0; f < 4; f++)
#pragma unroll
        for (int g = 0; g < 4; g++)
#pragma unroll
            for (int c = 0; c < 4; c++) acc[f][g][c] = 0.f;

    issue(0); asm volatile("cp.async.commit_group;");
    issue(1); asm volatile("cp.async.commit_group;");
    issue(2); asm volatile("cp.async.commit_group;");

    for (int kc = 0; kc < nchunk; kc++) {
        asm volatile("cp.async.wait_group 2;");
        __syncthreads();

        const int st = kc % NSTAGE;
        const uint32_t sA = s_u32 + (uint32_t)(st * STAGE_U16) * 2;
        const uint32_t sB = s_u32 + (uint32_t)((NSTAGE + st) * STAGE_U16) * 2;

#pragma unroll
        for (int ks = 0; ks < 32; ks += 16) {
            uint32_t af[4][4], bp[2][4];
#pragma unroll
            for (int f = 0; f < 4; f++) {
                uint32_t addr = sA + (uint32_t)(((wm + f * 16 + arow) * SPAD + ks + acol) * 2);
                asm volatile("ldmatrix.sync.aligned.m8n8.x4.shared.b16 {%0,%1,%2,%3}, [%4];"
                    : "=r"(af[f][0]), "=r"(af[f][1]), "=r"(af[f][2]), "=r"(af[f][3])
                    : "r"(addr));
            }
#pragma unroll
            for (int gp = 0; gp < 2; gp++) {
                uint32_t addr = sB + (uint32_t)(((wn + gp * 16 + brow) * SPAD + ks + bcol) * 2);
                asm volatile("ldmatrix.sync.aligned.m8n8.x4.shared.b16 {%0,%1,%2,%3}, [%4];"
                    : "=r"(bp[gp][0]), "=r"(bp[gp][1]), "=r"(bp[gp][2]), "=r"(bp[gp][3])
                    : "r"(addr));
            }
#pragma unroll
            for (int f = 0; f < 4; f++)
#pragma unroll
                for (int g = 0; g < 4; g++)
                    asm volatile(
                        "mma.sync.aligned.m16n8k16.row.col.f32.f16.f16.f32 "
                        "{%0,%1,%2,%3}, {%4,%5,%6,%7}, {%8,%9}, {%0,%1,%2,%3};"
                        : "+f"(acc[f][g][0]), "+f"(acc[f][g][1]),
                          "+f"(acc[f][g][2]), "+f"(acc[f][g][3])
                        : "r"(af[f][0]), "r"(af[f][1]), "r"(af[f][2]), "r"(af[f][3]),
                          "r"(bp[g >> 1][(g & 1) * 2]), "r"(bp[g >> 1][(g & 1) * 2 + 1]));
        }
        __syncthreads();
        if (kc + 3 < nchunk) issue(kc + 3);
        asm volatile("cp.async.commit_group;");
    }

#pragma unroll
    for (int f = 0; f < 4; f++) {
        const int r = wm + f * 16 + (lane >> 2);
#pragma unroll
        for (int g = 0; g < 4; g++) {
            const int c = wn + g * 8 + ((lane & 3) << 1);
            *(float2*)(Cout + (long long)r * DMODEL + c)       = make_float2(acc[f][g][0], acc[f][g][1]);
            *(float2*)(Cout + (long long)(r + 8) * DMODEL + c) = make_float2(acc[f][g][2], acc[f][g][3]);
        }
    }
}

// ---------------- split-K reduce fused with rhk -> fp16 double-split ----------------
__global__ __launch_bounds__(256) void reduce4_conv() {
    const size_t i = ((size_t)blockIdx.x * 256 + threadIdx.x) * 4;
    float4 a = *(const float4*)&g_rhk4[i];
    float4 b = *(const float4*)&g_rhk4[i + (size_t)KLEN * DMODEL];
    float4 c = *(const float4*)&g_rhk4[i + (size_t)2 * KLEN * DMODEL];
    float4 d = *(const float4*)&g_rhk4[i + (size_t)3 * KLEN * DMODEL];
    float4 s = make_float4(a.x + b.x + c.x + d.x, a.y + b.y + c.y + d.y,
                           a.z + b.z + c.z + d.z, a.w + b.w + c.w + d.w);
    *(float4*)&g_rhk[i] = s;

    const int j = (int)(i >> 10);
    const int e = (int)(i & 1023);
    const int n = e >> 6, d0 = e & 63;
    __half* dst = g_Bh + ((size_t)n * KLEN + j) * KH2;
    float v[4] = {s.x, s.y, s.z, s.w};
    __half hi[4], lo[4];
#pragma unroll
    for (int u = 0; u < 4; u++) {
        hi[u] = __float2half_rn(v[u]);
        lo[u] = __float2half_rn(v[u] - __half2float(hi[u]));
    }
    *(__half2*)(dst + d0)          = __halves2half2(hi[0], hi[1]);
    *(__half2*)(dst + d0 + 2)      = __halves2half2(hi[2], hi[3]);
    *(__half2*)(dst + 64 + d0)     = __halves2half2(lo[0], lo[1]);
    *(__half2*)(dst + 64 + d0 + 2) = __halves2half2(lo[2], lo[3]);
}

// ---------------- conversions ----------------
__global__ __launch_bounds__(256) void conv_mat_h(const float* __restrict__ in,
                                                  __half* __restrict__ outp) {
    const int r = blockIdx.x;
#pragma unroll
    for (int it = 0; it < 4; it++) {
        int e = threadIdx.x + it * 256;
        float x = in[(long long)r * 1024 + e];
        __half hi = __float2half_rn(x);
        __half lo = __float2half_rn(x - __half2float(hi));
        __half* dst = outp + (size_t)r * KH2BIG;
        dst[e] = hi;
        dst[1024 + e] = lo;
    }
}
__global__ __launch_bounds__(256) void conv_q_h(const float* __restrict__ q) {
    const int r = blockIdx.x;
#pragma unroll
    for (int it = 0; it < 4; it++) {
        int e = threadIdx.x + it * 256;
        int n = e >> 6, d = e & 63;
        float x = q[(long long)r * 1024 + e];
        __half hi = __float2half_rn(x);
        __half lo = __float2half_rn(x - __half2float(hi));
        __half* dst = g_Ah + ((size_t)n * MROWS + r) * KH2;
        dst[d] = hi;
        dst[64 + d] = lo;
    }
}

// ---------------- C[j,n] and D[j,n] bias terms ----------------
__global__ __launch_bounds__(512)
void bias_kernel(const float* __restrict__ whk,
                 const float* __restrict__ rwb,
                 const float* __restrict__ rrb)
{
    const int j = blockIdx.x;
    const int n = threadIdx.x >> 5;
    const int l = threadIdx.x & 31;

    float s = 0.f;
#pragma unroll
    for (int e = l; e < BSZ * DHEAD; e += 32) {
        int b = e >> 6, d = e & 63;
        s += rwb[n * DHEAD + d] * whk[(((j * BSZ + b) * NHEAD) + n) * DHEAD + d];
    }
    float sd = 0.f;
#pragma unroll
    for (int d = l; d < DHEAD; d += 32)
        sd += rrb[n * DHEAD + d] * g_rhk[j * DMODEL + n * DHEAD + d];

#pragma unroll
    for (int o = 16; o > 0; o >>= 1) {
        s  += __shfl_xor_sync(0xffffffffu, s,  o);
        sd += __shfl_xor_sync(0xffffffffu, sd, o);
    }
    if (l == 0) {
        g_C[j * NHEAD + n] = s;
        g_D[j * NHEAD + n] = sd;
    }
}

// ---------------- rel_shift gather + bias add + (b,n) transpose ----------------
__global__ __launch_bounds__(256)
void shuffle_kernel(float* __restrict__ out)
{
    __shared__ float sT[64][65];
    __shared__ float sCD[64][17];
    __shared__ int   sIpB[64];
    __shared__ int   sJq[64];

    const int t  = threadIdx.x;
    const int i  = blockIdx.y;
    const int j0 = blockIdx.x * 64;

    for (int idx = t; idx < 64 * NHEAD; idx += 256) {
        const int jl = idx >> 4;
        const int n  = idx & 15;
        const int j  = j0 + jl;
        const int pos = i * KLEN + j + QLEN;
        const int ip  = pos / (KLEN + 1);
        const int jp  = pos - ip * (KLEN + 1);
        float v = g_C[j * NHEAD + n];
        if (jp != 0) v += g_D[(jp - 1) * NHEAD + n];
        sCD[jl][n] = v;
        if (n == 0) { sIpB[jl] = ip * BSZ; sJq[jl] = jp - 1; }
    }
    __syncthreads();

    const int jj = t & 31;
    const int cb = t >> 5;

#pragma unroll
    for (int jc = 0; jc < 2; jc++) {
        const int jl  = jc * 32 + jj;
        const int jq  = sJq[jl];
        const int ipb = sIpB[jl];
#pragma unroll
        for (int u = 0; u < 8; u++) {
            const int c = cb + u * 8;   // c = b*16 + n
            const int b = c >> 4;
            const int n = c & 15;
            float v = sCD[jl][n];
            if (jq >= 0)
                v += __half2float(__ldcs(&g_B16[((size_t)n * MROWS + ipb + b) * KLEN + jq]));
            sT[jl][c] = v;
        }
    }
    __syncthreads();

#pragma unroll
    for (int w = 0; w < 4; w++) {
        const int jr = w * 16 + (t >> 4);
        const int c4 = (t & 15) * 4;
        float4 v = make_float4(sT[jr][c4], sT[jr][c4 + 1], sT[jr][c4 + 2], sT[jr][c4 + 3]);
        __stcs((float4*)(out + ((long long)i * KLEN + (j0 + jr)) * 64 + c4), v);
    }
}

// ---------------- launch ----------------
extern "C" void kernel_launch(void* const* d_in, const int* in_sizes, int n_in,
                              void* d_out, int out_size)
{
    const float* q   = (const float*)d_in[0];
    const float* whk = (const float*)d_in[1];
    const float* r   = (const float*)d_in[2];
    const float* Wr  = (const float*)d_in[3];
    const float* rwb = (const float*)d_in[4];
    const float* rrb = (const float*)d_in[5];
    float* out = (float*)d_out;
    (void)in_sizes; (void)n_in; (void)out_size;

    float *p_rhk4;
    __half *p_Ah, *p_Bh, *p_B16, *p_r2h, *p_Wr2h;
    cudaGetSymbolAddress((void**)&p_rhk4, g_rhk4);
    cudaGetSymbolAddress((void**)&p_B16,  g_B16);
    cudaGetSymbolAddress((void**)&p_Ah,   g_Ah);
    cudaGetSymbolAddress((void**)&p_Bh,   g_Bh);
    cudaGetSymbolAddress((void**)&p_r2h,  g_r2h);
    cudaGetSymbolAddress((void**)&p_Wr2h, g_Wr2h);

    cudaFuncSetAttribute(gemm_b128, cudaFuncAttributeMaxDynamicSharedMemorySize, GB_SMEM);
    cudaFuncSetAttribute(gemm_rhk,  cudaFuncAttributeMaxDynamicSharedMemorySize, RHK_SMEM);

    // conversions (fp16 double-split everywhere)
    conv_mat_h<<<KLEN,   256>>>(r,  p_r2h);
    conv_mat_h<<<DMODEL, 256>>>(Wr, p_Wr2h);
    conv_q_h  <<<MROWS,  256>>>(q);

    // 1) rhk = r.Wr^T, fp16 double-split, split-K=4 (M=2048,N=1024,K=512 each)
    gemm_rhk<<<dim3(DMODEL / 128, KLEN / 128, KSPLIT), 256, RHK_SMEM>>>(
        p_r2h, p_Wr2h, p_rhk4);
    reduce4_conv<<<(KLEN * DMODEL) / (256 * 4), 256>>>();

    // 2) C[j,n], D[j,n]
    bias_kernel<<<KLEN, 512>>>(whk, rwb, rrb);

    // 3) B[n][(i,b)][j] fp16 out  (per head: M=4096, N=2048, K=128)
    gemm_b128<<<dim3(KLEN / 128, MROWS / 128, NHEAD), 256, GB_SMEM>>>(
        p_Ah, p_Bh, p_B16);

    // 4) rel-shift gather + bias + transpose
    shuffle_kernel<<<dim3(KLEN / 64, QLEN), 256>>>(out);
}

// round 13
// speedup vs baseline: 2.4925x; 1.0100x over previous
#include <cuda_runtime.h>
#include <cuda_bf16.h>
#include <cuda_fp16.h>
#include <cstdint>

#define QLEN   1024
#define KLEN   2048
#define NHEAD  16
#define DHEAD  64
#define BSZ    4
#define DMODEL 1024
#define MROWS  (QLEN * BSZ)   // 4096 merged (i,b) rows
#define KH2BIG 2048           // 2*DMODEL (fp16 double-split rhk GEMM)
#define KSPLIT 4
#define KSLAB2 (KH2BIG / KSPLIT)  // 512
#define KH2    128            // 2*DHEAD (fp16 double-split gemm-B)

// ---------------- scratch ----------------
__device__ float g_rhk4[(size_t)KSPLIT * KLEN * DMODEL];      // split-K slabs (32MB)
__device__ float g_rhk[KLEN * DMODEL];                        // r_head_k [j][n*64+d]
__device__ __half g_B16[(size_t)NHEAD * MROWS * KLEN];        // B [n][(i,b)][j] fp16 (256MB)
__device__ float g_C[KLEN * NHEAD];
__device__ float g_D[KLEN * NHEAD];
__device__ __half g_Ah[(size_t)NHEAD * MROWS * KH2];          // q fp16:   [n][(i,b)][hi64|lo64]
__device__ __half g_Bh[(size_t)NHEAD * KLEN * KH2];           // rhk fp16: [n][j][hi64|lo64]
__device__ __half g_r2h[(size_t)KLEN * KH2BIG];               // r fp16:   [j][hi1024|lo1024]
__device__ __half g_Wr2h[(size_t)DMODEL * KH2BIG];            // W_r fp16: [nd][hi1024|lo1024]

__device__ __forceinline__ void cp_async16(uint32_t smem, const void* gptr) {
    asm volatile("cp.async.ca.shared.global [%0], [%1], 16;" :: "r"(smem), "l"(gptr));
}

// ================= gemm-B: K=128, A-resident, 4 B-tiles per CTA =================
// C[m][j] = sum_k A[m][k]*B[j][k], per-head. A tile (128xK128) stays in smem;
// 4 B n-tiles stream through a double-buffered cp.async pipeline. Epilogue of
// tile nt overlaps the fetch of tile nt+2.
#define SPB 136   // smem row stride fp16 (68 words): ldmatrix conflict-free
#define NT  4     // B tiles per CTA
#define TILE_U16 (128 * SPB)
#define GB_SMEM (3 * TILE_U16 * 2)   // A + 2 B buffers = 104448 B

__global__ __launch_bounds__(256)
void gemm_b128(const __half* __restrict__ Ag, const __half* __restrict__ Bg,
               __half* __restrict__ Cg)
{
    extern __shared__ __align__(16) uint16_t sm[];
    uint16_t* As = sm;                       // [128][SPB]
    // B buffers at sm + (1 + buf)*TILE_U16

    const int head = blockIdx.z;
    const __half* A  = Ag + (size_t)head * MROWS * KH2 + (blockIdx.y << 7) * KH2;
    const __half* Bb = Bg + (size_t)head * KLEN  * KH2 + (size_t)(blockIdx.x * (128 * NT)) * KH2;
    __half* Cout = Cg + (size_t)head * MROWS * KLEN
                      + (size_t)(blockIdx.y << 7) * KLEN + blockIdx.x * (128 * NT);

    const int t    = threadIdx.x;
    const int lane = t & 31;
    const int wid  = t >> 5;
    const int wm   = (wid & 1) * 64;
    const int wn   = (wid >> 1) * 32;

    const uint32_t s_u32 = (uint32_t)__cvta_generic_to_shared(sm);
    const int srow = t >> 4, sc8 = (t & 15) << 3;   // 8 chunks per thread per tile

    auto issueB = [&](int nt, int buf) {
        const uint32_t sB = s_u32 + (uint32_t)((1 + buf) * TILE_U16) * 2;
        const __half* Bt = Bb + (size_t)(nt * 128) * KH2;
#pragma unroll
        for (int u = 0; u < 8; u++) {
            int row = srow + u * 16;
            cp_async16(sB + (uint32_t)(row * SPB + sc8) * 2, Bt + (size_t)row * KH2 + sc8);
        }
    };

    // group 0: A + B0 ; group 1: B1
#pragma unroll
    for (int u = 0; u < 8; u++) {
        int row = srow + u * 16;
        cp_async16(s_u32 + (uint32_t)(row * SPB + sc8) * 2, A + (size_t)row * KH2 + sc8);
    }
    issueB(0, 0);
    asm volatile("cp.async.commit_group;");
    issueB(1, 1);
    asm volatile("cp.async.commit_group;");

    const int arow = lane & 15;
    const int acol = (lane >> 4) << 3;
    const int brow = (lane & 7) + ((lane >> 4) << 3);
    const int bcol = ((lane >> 3) & 1) << 3;

    for (int nt = 0; nt < NT; nt++) {
        asm volatile("cp.async.wait_group 1;");
        __syncthreads();

        const int buf = nt & 1;
        const uint32_t sB = s_u32 + (uint32_t)((1 + buf) * TILE_U16) * 2;

        float acc[4][4][4];
#pragma unroll
        for (int f = 0; f < 4; f++)
#pragma unroll
            for (int g = 0; g < 4; g++)
#pragma unroll
                for (int c = 0; c < 4; c++) acc[f][g][c] = 0.f;

#pragma unroll
        for (int ks = 0; ks < 128; ks += 16) {
            uint32_t af[4][4], bp[2][4];
#pragma unroll
            for (int f = 0; f < 4; f++) {
                uint32_t addr = s_u32 + (uint32_t)(((wm + f * 16 + arow) * SPB + ks + acol) * 2);
                asm volatile("ldmatrix.sync.aligned.m8n8.x4.shared.b16 {%0,%1,%2,%3}, [%4];"
                    : "=r"(af[f][0]), "=r"(af[f][1]), "=r"(af[f][2]), "=r"(af[f][3])
                    : "r"(addr));
            }
#pragma unroll
            for (int gp = 0; gp < 2; gp++) {
                uint32_t addr = sB + (uint32_t)(((wn + gp * 16 + brow) * SPB + ks + bcol) * 2);
                asm volatile("ldmatrix.sync.aligned.m8n8.x4.shared.b16 {%0,%1,%2,%3}, [%4];"
                    : "=r"(bp[gp][0]), "=r"(bp[gp][1]), "=r"(bp[gp][2]), "=r"(bp[gp][3])
                    : "r"(addr));
            }
#pragma unroll
            for (int f = 0; f < 4; f++)
#pragma unroll
                for (int g = 0; g < 4; g++)
                    asm volatile(
                        "mma.sync.aligned.m16n8k16.row.col.f32.f16.f16.f32 "
                        "{%0,%1,%2,%3}, {%4,%5,%6,%7}, {%8,%9}, {%0,%1,%2,%3};"
                        : "+f"(acc[f][g][0]), "+f"(acc[f][g][1]),
                          "+f"(acc[f][g][2]), "+f"(acc[f][g][3])
                        : "r"(af[f][0]), "r"(af[f][1]), "r"(af[f][2]), "r"(af[f][3]),
                          "r"(bp[g >> 1][(g & 1) * 2]), "r"(bp[g >> 1][(g & 1) * 2 + 1]));
        }
        __syncthreads();

        if (nt + 2 < NT) issueB(nt + 2, buf);
        asm volatile("cp.async.commit_group;");

        // epilogue for this tile (regs only; overlaps next B fetch)
        __half* Ct = Cout + nt * 128;
#pragma unroll
        for (int f = 0; f < 4; f++) {
            const int r = wm + f * 16 + (lane >> 2);
#pragma unroll
            for (int g = 0; g < 4; g++) {
                const int c = wn + g * 8 + ((lane & 3) << 1);
                *(__half2*)(Ct + (size_t)r * KLEN + c)       = __floats2half2_rn(acc[f][g][0], acc[f][g][1]);
                *(__half2*)(Ct + (size_t)(r + 8) * KLEN + c) = __floats2half2_rn(acc[f][g][2], acc[f][g][3]);
            }
        }
    }
}

// ================= rhk GEMM: 3-stage cp.async pipeline, BK=32 (R11 config) =================
#define SPAD 40
#define STAGE_U16 (128 * SPAD)                 // per tile per stage (uint16)
#define RHK_SMEM  (6 * STAGE_U16 * 2)          // 61440 B

__global__ __launch_bounds__(256)
void gemm_rhk(const __half* __restrict__ Ag, const __half* __restrict__ Bg,
              float* __restrict__ Cg)
{
    extern __shared__ __align__(16) uint16_t sm[];

    const __half* A = Ag + (long long)blockIdx.z * KSLAB2 + (blockIdx.y << 7) * KH2BIG;
    const __half* B = Bg + (long long)blockIdx.z * KSLAB2 + (blockIdx.x << 7) * KH2BIG;
    float* Cout = Cg + (long long)blockIdx.z * KLEN * DMODEL
                     + (long long)(blockIdx.y << 7) * DMODEL + (blockIdx.x << 7);

    const int t    = threadIdx.x;
    const int lane = t & 31;
    const int wid  = t >> 5;
    const int wm   = (wid & 1) * 64;
    const int wn   = (wid >> 1) * 32;
    const int nchunk = KSLAB2 / 32;   // 16

    const uint32_t s_u32 = (uint32_t)__cvta_generic_to_shared(sm);
    const int srow = t >> 2, sc8 = (t & 3) << 3;

    auto issue = [&](int kc) {
        const int st = kc % 3;
        const uint32_t sA = s_u32 + (uint32_t)(st * STAGE_U16) * 2;
        const uint32_t sB = s_u32 + (uint32_t)((3 + st) * STAGE_U16) * 2;
        const int ko = kc << 5;
#pragma unroll
        for (int u = 0; u < 2; u++) {
            int row = srow + u * 64;
            cp_async16(sA + (uint32_t)(row * SPAD + sc8) * 2, A + (long long)row * KH2BIG + ko + sc8);
            cp_async16(sB + (uint32_t)(row * SPAD + sc8) * 2, B + (long long)row * KH2BIG + ko + sc8);
        }
    };

    const int arow = lane & 15;
    const int acol = (lane >> 4) << 3;
    const int brow = (lane & 7) + ((lane >> 4) << 3);
    const int bcol = ((lane >> 3) & 1) << 3;

    float acc[4][4][4];
#pragma unroll
    for (int f = 0; f < 4; f++)
#pragma unroll
        for (int g = 0; g < 4; g++)
#pragma unroll
            for (int c = 0; c < 4; c++) acc[f][g][c] = 0.f;

    issue(0); asm volatile("cp.async.commit_group;");
    issue(1); asm volatile("cp.async.commit_group;");

    for (int kc = 0; kc < nchunk; kc++) {
        asm volatile("cp.async.wait_group 1;");
        __syncthreads();

        const int st = kc % 3;
        const uint32_t sA = s_u32 + (uint32_t)(st * STAGE_U16) * 2;
        const uint32_t sB = s_u32 + (uint32_t)((3 + st) * STAGE_U16) * 2;

#pragma unroll
        for (int ks = 0; ks < 32; ks += 16) {
            uint32_t af[4][4], bp[2][4];
#pragma unroll
            for (int f = 0; f < 4; f++) {
                uint32_t addr = sA + (uint32_t)(((wm + f * 16 + arow) * SPAD + ks + acol) * 2);
                asm volatile("ldmatrix.sync.aligned.m8n8.x4.shared.b16 {%0,%1,%2,%3}, [%4];"
                    : "=r"(af[f][0]), "=r"(af[f][1]), "=r"(af[f][2]), "=r"(af[f][3])
                    : "r"(addr));
            }
#pragma unroll
            for (int gp = 0; gp < 2; gp++) {
                uint32_t addr = sB + (uint32_t)(((wn + gp * 16 + brow) * SPAD + ks + bcol) * 2);
                asm volatile("ldmatrix.sync.aligned.m8n8.x4.shared.b16 {%0,%1,%2,%3}, [%4];"
                    : "=r"(bp[gp][0]), "=r"(bp[gp][1]), "=r"(bp[gp][2]), "=r"(bp[gp][3])
                    : "r"(addr));
            }
#pragma unroll
            for (int f = 0; f < 4; f++)
#pragma unroll
                for (int g = 0; g < 4; g++)
                    asm volatile(
                        "mma.sync.aligned.m16n8k16.row.col.f32.f16.f16.f32 "
                        "{%0,%1,%2,%3}, {%4,%5,%6,%7}, {%8,%9}, {%0,%1,%2,%3};"
                        : "+f"(acc[f][g][0]), "+f"(acc[f][g][1]),
                          "+f"(acc[f][g][2]), "+f"(acc[f][g][3])
                        : "r"(af[f][0]), "r"(af[f][1]), "r"(af[f][2]), "r"(af[f][3]),
                          "r"(bp[g >> 1][(g & 1) * 2]), "r"(bp[g >> 1][(g & 1) * 2 + 1]));
        }
        __syncthreads();
        if (kc + 2 < nchunk) issue(kc + 2);
        asm volatile("cp.async.commit_group;");
    }

#pragma unroll
    for (int f = 0; f < 4; f++) {
        const int r = wm + f * 16 + (lane >> 2);
#pragma unroll
        for (int g = 0; g < 4; g++) {
            const int c = wn + g * 8 + ((lane & 3) << 1);
            *(float2*)(Cout + (long long)r * DMODEL + c)       = make_float2(acc[f][g][0], acc[f][g][1]);
            *(float2*)(Cout + (long long)(r + 8) * DMODEL + c) = make_float2(acc[f][g][2], acc[f][g][3]);
        }
    }
}

// ---------------- split-K reduce fused with rhk -> fp16 double-split ----------------
__global__ __launch_bounds__(256) void reduce4_conv() {
    const size_t i = ((size_t)blockIdx.x * 256 + threadIdx.x) * 4;
    float4 a = *(const float4*)&g_rhk4[i];
    float4 b = *(const float4*)&g_rhk4[i + (size_t)KLEN * DMODEL];
    float4 c = *(const float4*)&g_rhk4[i + (size_t)2 * KLEN * DMODEL];
    float4 d = *(const float4*)&g_rhk4[i + (size_t)3 * KLEN * DMODEL];
    float4 s = make_float4(a.x + b.x + c.x + d.x, a.y + b.y + c.y + d.y,
                           a.z + b.z + c.z + d.z, a.w + b.w + c.w + d.w);
    *(float4*)&g_rhk[i] = s;

    const int j = (int)(i >> 10);
    const int e = (int)(i & 1023);
    const int n = e >> 6, d0 = e & 63;
    __half* dst = g_Bh + ((size_t)n * KLEN + j) * KH2;
    float v[4] = {s.x, s.y, s.z, s.w};
    __half hi[4], lo[4];
#pragma unroll
    for (int u = 0; u < 4; u++) {
        hi[u] = __float2half_rn(v[u]);
        lo[u] = __float2half_rn(v[u] - __half2float(hi[u]));
    }
    *(__half2*)(dst + d0)          = __halves2half2(hi[0], hi[1]);
    *(__half2*)(dst + d0 + 2)      = __halves2half2(hi[2], hi[3]);
    *(__half2*)(dst + 64 + d0)     = __halves2half2(lo[0], lo[1]);
    *(__half2*)(dst + 64 + d0 + 2) = __halves2half2(lo[2], lo[3]);
}

// ---------------- conversions ----------------
__global__ __launch_bounds__(256) void conv_mat_h(const float* __restrict__ in,
                                                  __half* __restrict__ outp) {
    const int r = blockIdx.x;
#pragma unroll
    for (int it = 0; it < 4; it++) {
        int e = threadIdx.x + it * 256;
        float x = in[(long long)r * 1024 + e];
        __half hi = __float2half_rn(x);
        __half lo = __float2half_rn(x - __half2float(hi));
        __half* dst = outp + (size_t)r * KH2BIG;
        dst[e] = hi;
        dst[1024 + e] = lo;
    }
}
__global__ __launch_bounds__(256) void conv_q_h(const float* __restrict__ q) {
    const int r = blockIdx.x;
#pragma unroll
    for (int it = 0; it < 4; it++) {
        int e = threadIdx.x + it * 256;
        int n = e >> 6, d = e & 63;
        float x = q[(long long)r * 1024 + e];
        __half hi = __float2half_rn(x);
        __half lo = __float2half_rn(x - __half2float(hi));
        __half* dst = g_Ah + ((size_t)n * MROWS + r) * KH2;
        dst[d] = hi;
        dst[64 + d] = lo;
    }
}

// ---------------- C[j,n] and D[j,n] bias terms ----------------
__global__ __launch_bounds__(512)
void bias_kernel(const float* __restrict__ whk,
                 const float* __restrict__ rwb,
                 const float* __restrict__ rrb)
{
    const int j = blockIdx.x;
    const int n = threadIdx.x >> 5;
    const int l = threadIdx.x & 31;

    float s = 0.f;
#pragma unroll
    for (int e = l; e < BSZ * DHEAD; e += 32) {
        int b = e >> 6, d = e & 63;
        s += rwb[n * DHEAD + d] * whk[(((j * BSZ + b) * NHEAD) + n) * DHEAD + d];
    }
    float sd = 0.f;
#pragma unroll
    for (int d = l; d < DHEAD; d += 32)
        sd += rrb[n * DHEAD + d] * g_rhk[j * DMODEL + n * DHEAD + d];

#pragma unroll
    for (int o = 16; o > 0; o >>= 1) {
        s  += __shfl_xor_sync(0xffffffffu, s,  o);
        sd += __shfl_xor_sync(0xffffffffu, sd, o);
    }
    if (l == 0) {
        g_C[j * NHEAD + n] = s;
        g_D[j * NHEAD + n] = sd;
    }
}

// ---------------- rel_shift gather + bias add + (b,n) transpose ----------------
__global__ __launch_bounds__(256)
void shuffle_kernel(float* __restrict__ out)
{
    __shared__ float sT[64][65];
    __shared__ float sCD[64][17];
    __shared__ int   sIpB[64];
    __shared__ int   sJq[64];

    const int t  = threadIdx.x;
    const int i  = blockIdx.y;
    const int j0 = blockIdx.x * 64;

    for (int idx = t; idx < 64 * NHEAD; idx += 256) {
        const int jl = idx >> 4;
        const int n  = idx & 15;
        const int j  = j0 + jl;
        const int pos = i * KLEN + j + QLEN;
        const int ip  = pos / (KLEN + 1);
        const int jp  = pos - ip * (KLEN + 1);
        float v = g_C[j * NHEAD + n];
        if (jp != 0) v += g_D[(jp - 1) * NHEAD + n];
        sCD[jl][n] = v;
        if (n == 0) { sIpB[jl] = ip * BSZ; sJq[jl] = jp - 1; }
    }
    __syncthreads();

    const int jj = t & 31;
    const int cb = t >> 5;

#pragma unroll
    for (int jc = 0; jc < 2; jc++) {
        const int jl  = jc * 32 + jj;
        const int jq  = sJq[jl];
        const int ipb = sIpB[jl];
#pragma unroll
        for (int u = 0; u < 8; u++) {
            const int c = cb + u * 8;   // c = b*16 + n
            const int b = c >> 4;
            const int n = c & 15;
            float v = sCD[jl][n];
            if (jq >= 0)
                v += __half2float(__ldcs(&g_B16[((size_t)n * MROWS + ipb + b) * KLEN + jq]));
            sT[jl][c] = v;
        }
    }
    __syncthreads();

#pragma unroll
    for (int w = 0; w < 4; w++) {
        const int jr = w * 16 + (t >> 4);
        const int c4 = (t & 15) * 4;
        float4 v = make_float4(sT[jr][c4], sT[jr][c4 + 1], sT[jr][c4 + 2], sT[jr][c4 + 3]);
        __stcs((float4*)(out + ((long long)i * KLEN + (j0 + jr)) * 64 + c4), v);
    }
}

// ---------------- launch ----------------
extern "C" void kernel_launch(void* const* d_in, const int* in_sizes, int n_in,
                              void* d_out, int out_size)
{
    const float* q   = (const float*)d_in[0];
    const float* whk = (const float*)d_in[1];
    const float* r   = (const float*)d_in[2];
    const float* Wr  = (const float*)d_in[3];
    const float* rwb = (const float*)d_in[4];
    const float* rrb = (const float*)d_in[5];
    float* out = (float*)d_out;
    (void)in_sizes; (void)n_in; (void)out_size;

    float *p_rhk4;
    __half *p_Ah, *p_Bh, *p_B16, *p_r2h, *p_Wr2h;
    cudaGetSymbolAddress((void**)&p_rhk4, g_rhk4);
    cudaGetSymbolAddress((void**)&p_B16,  g_B16);
    cudaGetSymbolAddress((void**)&p_Ah,   g_Ah);
    cudaGetSymbolAddress((void**)&p_Bh,   g_Bh);
    cudaGetSymbolAddress((void**)&p_r2h,  g_r2h);
    cudaGetSymbolAddress((void**)&p_Wr2h, g_Wr2h);

    cudaFuncSetAttribute(gemm_b128, cudaFuncAttributeMaxDynamicSharedMemorySize, GB_SMEM);
    cudaFuncSetAttribute(gemm_rhk,  cudaFuncAttributeMaxDynamicSharedMemorySize, RHK_SMEM);

    // conversions (fp16 double-split everywhere)
    conv_mat_h<<<KLEN,   256>>>(r,  p_r2h);
    conv_mat_h<<<DMODEL, 256>>>(Wr, p_Wr2h);
    conv_q_h  <<<MROWS,  256>>>(q);

    // 1) rhk = r.Wr^T, fp16 double-split, split-K=4 (M=2048,N=1024,K=512 each)
    gemm_rhk<<<dim3(DMODEL / 128, KLEN / 128, KSPLIT), 256, RHK_SMEM>>>(
        p_r2h, p_Wr2h, p_rhk4);
    reduce4_conv<<<(KLEN * DMODEL) / (256 * 4), 256>>>();

    // 2) C[j,n], D[j,n]
    bias_kernel<<<KLEN, 512>>>(whk, rwb, rrb);

    // 3) B[n][(i,b)][j] fp16 out (per head: M=4096, N=2048, K=128; 4 B tiles/CTA)
    gemm_b128<<<dim3(KLEN / (128 * NT), MROWS / 128, NHEAD), 256, GB_SMEM>>>(
        p_Ah, p_Bh, p_B16);

    // 4) rel-shift gather + bias + transpose
    shuffle_kernel<<<dim3(KLEN / 64, QLEN), 256>>>(out);
}

// round 15
// speedup vs baseline: 2.5090x; 1.0066x over previous
#include <cuda_runtime.h>
#include <cuda_bf16.h>
#include <cuda_fp16.h>
#include <cstdint>

#define QLEN   1024
#define KLEN   2048
#define NHEAD  16
#define DHEAD  64
#define BSZ    4
#define DMODEL 1024
#define MROWS  (QLEN * BSZ)   // 4096 merged (i,b) rows
#define KH2BIG 2048           // 2*DMODEL (fp16 double-split rhk GEMM)
#define KSPLIT 4
#define KSLAB2 (KH2BIG / KSPLIT)  // 512
#define KH2    128            // 2*DHEAD (fp16 double-split gemm-B)

// ---------------- scratch ----------------
__device__ float g_rhk4[(size_t)KSPLIT * KLEN * DMODEL];      // split-K slabs (32MB)
__device__ __half g_B16[(size_t)NHEAD * MROWS * KLEN];        // B [n][(i,b)][j] fp16 (256MB)
__device__ float g_C[KLEN * NHEAD];
__device__ float g_D[KLEN * NHEAD];
__device__ __half g_Ah[(size_t)NHEAD * MROWS * KH2];          // q fp16:   [n][(i,b)][hi64|lo64]
__device__ __half g_Bh[(size_t)NHEAD * KLEN * KH2];           // rhk fp16: [n][j][hi64|lo64]
__device__ __half g_r2h[(size_t)KLEN * KH2BIG];               // r fp16:   [j][hi1024|lo1024]
__device__ __half g_Wr2h[(size_t)DMODEL * KH2BIG];            // W_r fp16: [nd][hi1024|lo1024]

__device__ __forceinline__ void cp_async16(uint32_t smem, const void* gptr) {
    asm volatile("cp.async.ca.shared.global [%0], [%1], 16;" :: "r"(smem), "l"(gptr));
}

// ================= gemm-B: K=128, A-resident, 8 B-tiles per CTA =================
#define SPB 136   // smem row stride fp16 (68 words): ldmatrix conflict-free
#define NT  8     // B tiles per CTA
#define TILE_U16 (128 * SPB)
#define GB_SMEM (3 * TILE_U16 * 2)   // A + 2 B buffers = 104448 B

__global__ __launch_bounds__(256)
void gemm_b128(const __half* __restrict__ Ag, const __half* __restrict__ Bg,
               __half* __restrict__ Cg)
{
    extern __shared__ __align__(16) uint16_t sm[];

    const int head = blockIdx.z;
    const __half* A  = Ag + (size_t)head * MROWS * KH2 + (blockIdx.y << 7) * KH2;
    const __half* Bb = Bg + (size_t)head * KLEN  * KH2 + (size_t)(blockIdx.x * (128 * NT)) * KH2;
    __half* Cout = Cg + (size_t)head * MROWS * KLEN
                      + (size_t)(blockIdx.y << 7) * KLEN + blockIdx.x * (128 * NT);

    const int t    = threadIdx.x;
    const int lane = t & 31;
    const int wid  = t >> 5;
    const int wm   = (wid & 1) * 64;
    const int wn   = (wid >> 1) * 32;

    const uint32_t s_u32 = (uint32_t)__cvta_generic_to_shared(sm);
    const int srow = t >> 4, sc8 = (t & 15) << 3;   // 8 chunks per thread per tile

    auto issueB = [&](int nt, int buf) {
        const uint32_t sB = s_u32 + (uint32_t)((1 + buf) * TILE_U16) * 2;
        const __half* Bt = Bb + (size_t)(nt * 128) * KH2;
#pragma unroll
        for (int u = 0; u < 8; u++) {
            int row = srow + u * 16;
            cp_async16(sB + (uint32_t)(row * SPB + sc8) * 2, Bt + (size_t)row * KH2 + sc8);
        }
    };

#pragma unroll
    for (int u = 0; u < 8; u++) {
        int row = srow + u * 16;
        cp_async16(s_u32 + (uint32_t)(row * SPB + sc8) * 2, A + (size_t)row * KH2 + sc8);
    }
    issueB(0, 0);
    asm volatile("cp.async.commit_group;");
    issueB(1, 1);
    asm volatile("cp.async.commit_group;");

    const int arow = lane & 15;
    const int acol = (lane >> 4) << 3;
    const int brow = (lane & 7) + ((lane >> 4) << 3);
    const int bcol = ((lane >> 3) & 1) << 3;

    for (int nt = 0; nt < NT; nt++) {
        asm volatile("cp.async.wait_group 1;");
        __syncthreads();

        const int buf = nt & 1;
        const uint32_t sB = s_u32 + (uint32_t)((1 + buf) * TILE_U16) * 2;

        float acc[4][4][4];
#pragma unroll
        for (int f = 0; f < 4; f++)
#pragma unroll
            for (int g = 0; g < 4; g++)
#pragma unroll
                for (int c = 0; c < 4; c++) acc[f][g][c] = 0.f;

#pragma unroll
        for (int ks = 0; ks < 128; ks += 16) {
            uint32_t af[4][4], bp[2][4];
#pragma unroll
            for (int f = 0; f < 4; f++) {
                uint32_t addr = s_u32 + (uint32_t)(((wm + f * 16 + arow) * SPB + ks + acol) * 2);
                asm volatile("ldmatrix.sync.aligned.m8n8.x4.shared.b16 {%0,%1,%2,%3}, [%4];"
                    : "=r"(af[f][0]), "=r"(af[f][1]), "=r"(af[f][2]), "=r"(af[f][3])
                    : "r"(addr));
            }
#pragma unroll
            for (int gp = 0; gp < 2; gp++) {
                uint32_t addr = sB + (uint32_t)(((wn + gp * 16 + brow) * SPB + ks + bcol) * 2);
                asm volatile("ldmatrix.sync.aligned.m8n8.x4.shared.b16 {%0,%1,%2,%3}, [%4];"
                    : "=r"(bp[gp][0]), "=r"(bp[gp][1]), "=r"(bp[gp][2]), "=r"(bp[gp][3])
                    : "r"(addr));
            }
#pragma unroll
            for (int f = 0; f < 4; f++)
#pragma unroll
                for (int g = 0; g < 4; g++)
                    asm volatile(
                        "mma.sync.aligned.m16n8k16.row.col.f32.f16.f16.f32 "
                        "{%0,%1,%2,%3}, {%4,%5,%6,%7}, {%8,%9}, {%0,%1,%2,%3};"
                        : "+f"(acc[f][g][0]), "+f"(acc[f][g][1]),
                          "+f"(acc[f][g][2]), "+f"(acc[f][g][3])
                        : "r"(af[f][0]), "r"(af[f][1]), "r"(af[f][2]), "r"(af[f][3]),
                          "r"(bp[g >> 1][(g & 1) * 2]), "r"(bp[g >> 1][(g & 1) * 2 + 1]));
        }
        __syncthreads();

        if (nt + 2 < NT) issueB(nt + 2, buf);
        asm volatile("cp.async.commit_group;");

        __half* Ct = Cout + nt * 128;
#pragma unroll
        for (int f = 0; f < 4; f++) {
            const int r = wm + f * 16 + (lane >> 2);
#pragma unroll
            for (int g = 0; g < 4; g++) {
                const int c = wn + g * 8 + ((lane & 3) << 1);
                *(__half2*)(Ct + (size_t)r * KLEN + c)       = __floats2half2_rn(acc[f][g][0], acc[f][g][1]);
                *(__half2*)(Ct + (size_t)(r + 8) * KLEN + c) = __floats2half2_rn(acc[f][g][2], acc[f][g][3]);
            }
        }
    }
}

// ================= rhk GEMM: 3-stage cp.async pipeline, BK=32 =================
#define SPAD 40
#define STAGE_U16 (128 * SPAD)
#define RHK_SMEM  (6 * STAGE_U16 * 2)          // 61440 B

__global__ __launch_bounds__(256)
void gemm_rhk(const __half* __restrict__ Ag, const __half* __restrict__ Bg,
              float* __restrict__ Cg)
{
    extern __shared__ __align__(16) uint16_t sm[];

    const __half* A = Ag + (long long)blockIdx.z * KSLAB2 + (blockIdx.y << 7) * KH2BIG;
    const __half* B = Bg + (long long)blockIdx.z * KSLAB2 + (blockIdx.x << 7) * KH2BIG;
    float* Cout = Cg + (long long)blockIdx.z * KLEN * DMODEL
                     + (long long)(blockIdx.y << 7) * DMODEL + (blockIdx.x << 7);

    const int t    = threadIdx.x;
    const int lane = t & 31;
    const int wid  = t >> 5;
    const int wm   = (wid & 1) * 64;
    const int wn   = (wid >> 1) * 32;
    const int nchunk = KSLAB2 / 32;   // 16

    const uint32_t s_u32 = (uint32_t)__cvta_generic_to_shared(sm);
    const int srow = t >> 2, sc8 = (t & 3) << 3;

    auto issue = [&](int kc) {
        const int st = kc % 3;
        const uint32_t sA = s_u32 + (uint32_t)(st * STAGE_U16) * 2;
        const uint32_t sB = s_u32 + (uint32_t)((3 + st) * STAGE_U16) * 2;
        const int ko = kc << 5;
#pragma unroll
        for (int u = 0; u < 2; u++) {
            int row = srow + u * 64;
            cp_async16(sA + (uint32_t)(row * SPAD + sc8) * 2, A + (long long)row * KH2BIG + ko + sc8);
            cp_async16(sB + (uint32_t)(row * SPAD + sc8) * 2, B + (long long)row * KH2BIG + ko + sc8);
        }
    };

    const int arow = lane & 15;
    const int acol = (lane >> 4) << 3;
    const int brow = (lane & 7) + ((lane >> 4) << 3);
    const int bcol = ((lane >> 3) & 1) << 3;

    float acc[4][4][4];
#pragma unroll
    for (int f = 0; f < 4; f++)
#pragma unroll
        for (int g = 0; g < 4; g++)
#pragma unroll
            for (int c = 0; c < 4; c++) acc[f][g][c] = 0.f;

    issue(0); asm volatile("cp.async.commit_group;");
    issue(1); asm volatile("cp.async.commit_group;");

    for (int kc = 0; kc < nchunk; kc++) {
        asm volatile("cp.async.wait_group 1;");
        __syncthreads();

        const int st = kc % 3;
        const uint32_t sA = s_u32 + (uint32_t)(st * STAGE_U16) * 2;
        const uint32_t sB = s_u32 + (uint32_t)((3 + st) * STAGE_U16) * 2;

#pragma unroll
        for (int ks = 0; ks < 32; ks += 16) {
            uint32_t af[4][4], bp[2][4];
#pragma unroll
            for (int f = 0; f < 4; f++) {
                uint32_t addr = sA + (uint32_t)(((wm + f * 16 + arow) * SPAD + ks + acol) * 2);
                asm volatile("ldmatrix.sync.aligned.m8n8.x4.shared.b16 {%0,%1,%2,%3}, [%4];"
                    : "=r"(af[f][0]), "=r"(af[f][1]), "=r"(af[f][2]), "=r"(af[f][3])
                    : "r"(addr));
            }
#pragma unroll
            for (int gp = 0; gp < 2; gp++) {
                uint32_t addr = sB + (uint32_t)(((wn + gp * 16 + brow) * SPAD + ks + bcol) * 2);
                asm volatile("ldmatrix.sync.aligned.m8n8.x4.shared.b16 {%0,%1,%2,%3}, [%4];"
                    : "=r"(bp[gp][0]), "=r"(bp[gp][1]), "=r"(bp[gp][2]), "=r"(bp[gp][3])
                    : "r"(addr));
            }
#pragma unroll
            for (int f = 0; f < 4; f++)
#pragma unroll
                for (int g = 0; g < 4; g++)
                    asm volatile(
                        "mma.sync.aligned.m16n8k16.row.col.f32.f16.f16.f32 "
                        "{%0,%1,%2,%3}, {%4,%5,%6,%7}, {%8,%9}, {%0,%1,%2,%3};"
                        : "+f"(acc[f][g][0]), "+f"(acc[f][g][1]),
                          "+f"(acc[f][g][2]), "+f"(acc[f][g][3])
                        : "r"(af[f][0]), "r"(af[f][1]), "r"(af[f][2]), "r"(af[f][3]),
                          "r"(bp[g >> 1][(g & 1) * 2]), "r"(bp[g >> 1][(g & 1) * 2 + 1]));
        }
        __syncthreads();
        if (kc + 2 < nchunk) issue(kc + 2);
        asm volatile("cp.async.commit_group;");
    }

#pragma unroll
    for (int f = 0; f < 4; f++) {
        const int r = wm + f * 16 + (lane >> 2);
#pragma unroll
        for (int g = 0; g < 4; g++) {
            const int c = wn + g * 8 + ((lane & 3) << 1);
            *(float2*)(Cout + (long long)r * DMODEL + c)       = make_float2(acc[f][g][0], acc[f][g][1]);
            *(float2*)(Cout + (long long)(r + 8) * DMODEL + c) = make_float2(acc[f][g][2], acc[f][g][3]);
        }
    }
}

// ---------------- fused: split-K reduce + fp16 split + D bias ----------------
__global__ __launch_bounds__(256) void reduce4_conv_bias(const float* __restrict__ rrb) {
    const int j = blockIdx.x;
    const int t = threadIdx.x;
    const size_t i = (size_t)j * 1024 + t * 4;
    float4 a = *(const float4*)&g_rhk4[i];
    float4 b = *(const float4*)&g_rhk4[i + (size_t)KLEN * DMODEL];
    float4 c = *(const float4*)&g_rhk4[i + (size_t)2 * KLEN * DMODEL];
    float4 d = *(const float4*)&g_rhk4[i + (size_t)3 * KLEN * DMODEL];
    float v[4] = {a.x + b.x + c.x + d.x, a.y + b.y + c.y + d.y,
                  a.z + b.z + c.z + d.z, a.w + b.w + c.w + d.w};

    const int e = t * 4;
    const int n = e >> 6, d0 = e & 63;
    __half* dst = g_Bh + ((size_t)n * KLEN + j) * KH2;
    __half hi[4], lo[4];
    float sd = 0.f;
#pragma unroll
    for (int u = 0; u < 4; u++) {
        hi[u] = __float2half_rn(v[u]);
        lo[u] = __float2half_rn(v[u] - __half2float(hi[u]));
        sd += v[u] * rrb[n * DHEAD + d0 + u];
    }
    *(__half2*)(dst + d0)          = __halves2half2(hi[0], hi[1]);
    *(__half2*)(dst + d0 + 2)      = __halves2half2(hi[2], hi[3]);
    *(__half2*)(dst + 64 + d0)     = __halves2half2(lo[0], lo[1]);
    *(__half2*)(dst + 64 + d0 + 2) = __halves2half2(lo[2], lo[3]);

#pragma unroll
    for (int o = 8; o > 0; o >>= 1)
        sd += __shfl_xor_sync(0xffffffffu, sd, o);
    if ((t & 15) == 0) g_D[j * NHEAD + n] = sd;
}

// ---------------- fused conversions + C bias ----------------
// blocks [0,2048): r rows -> g_r2h ; [2048,3072): Wr rows -> g_Wr2h ;
// [3072,7168): q rows -> g_Ah ; [7168,9216): C[j][n] from whk.
__global__ __launch_bounds__(256)
void conv_all(const float* __restrict__ r, const float* __restrict__ Wr,
              const float* __restrict__ q, const float* __restrict__ whk,
              const float* __restrict__ rwb)
{
    const int blk = blockIdx.x;
    const int t = threadIdx.x;
    if (blk < 7168) {
        const float* in;
        int row;
        if (blk < 2048)      { in = r;  row = blk; }
        else if (blk < 3072) { in = Wr; row = blk - 2048; }
        else                 { in = q;  row = blk - 3072; }
#pragma unroll
        for (int it = 0; it < 4; it++) {
            int e = t + it * 256;
            float x = in[(size_t)row * 1024 + e];
            __half hi = __float2half_rn(x);
            __half lo = __float2half_rn(x - __half2float(hi));
            if (blk < 3072) {
                __half* dst = (blk < 2048 ? g_r2h : g_Wr2h) + (size_t)row * KH2BIG;
                dst[e] = hi;
                dst[1024 + e] = lo;
            } else {
                int n = e >> 6, dd = e & 63;
                __half* dst = g_Ah + ((size_t)n * MROWS + row) * KH2;
                dst[dd] = hi;
                dst[64 + dd] = lo;
            }
        }
    } else {
        // C[j][n] = sum_{b,d} rwb[n,d] * whk[j,b,n,d]; whk row j = 4096 floats
        const int j = blk - 7168;
        const int n = t >> 4, s = t & 15;
        const float* row = whk + (size_t)j * (BSZ * NHEAD * DHEAD);
        float sum = 0.f;
#pragma unroll
        for (int k = 0; k < 16; k++) {
            int e = s + k * 16;           // e enumerates (b,d): b = e>>6, d = e&63
            sum += rwb[n * DHEAD + (e & 63)] * row[(e >> 6) * (NHEAD * DHEAD) + n * DHEAD + (e & 63)];
        }
#pragma unroll
        for (int o = 8; o > 0; o >>= 1)
            sum += __shfl_xor_sync(0xffffffffu, sum, o);
        if (s == 0) g_C[j * NHEAD + n] = sum;
    }
}

// ---------------- rel_shift gather + bias add + (b,n) transpose ----------------
__global__ __launch_bounds__(256)
void shuffle_kernel(float* __restrict__ out)
{
    __shared__ float sT[64][65];
    __shared__ float sCD[64][17];
    __shared__ int   sIpB[64];
    __shared__ int   sJq[64];

    const int t  = threadIdx.x;
    const int i  = blockIdx.y;
    const int j0 = blockIdx.x * 64;

    for (int idx = t; idx < 64 * NHEAD; idx += 256) {
        const int jl = idx >> 4;
        const int n  = idx & 15;
        const int j  = j0 + jl;
        const int pos = i * KLEN + j + QLEN;
        const int ip  = pos / (KLEN + 1);
        const int jp  = pos - ip * (KLEN + 1);
        float v = g_C[j * NHEAD + n];
        if (jp != 0) v += g_D[(jp - 1) * NHEAD + n];
        sCD[jl][n] = v;
        if (n == 0) { sIpB[jl] = ip * BSZ; sJq[jl] = jp - 1; }
    }
    __syncthreads();

    const int jj = t & 31;
    const int cb = t >> 5;

#pragma unroll
    for (int jc = 0; jc < 2; jc++) {
        const int jl  = jc * 32 + jj;
        const int jq  = sJq[jl];
        const int ipb = sIpB[jl];
#pragma unroll
        for (int u = 0; u < 8; u++) {
            const int c = cb + u * 8;   // c = b*16 + n
            const int b = c >> 4;
            const int n = c & 15;
            float v = sCD[jl][n];
            if (jq >= 0)
                v += __half2float(__ldcs(&g_B16[((size_t)n * MROWS + ipb + b) * KLEN + jq]));
            sT[jl][c] = v;
        }
    }
    __syncthreads();

#pragma unroll
    for (int w = 0; w < 4; w++) {
        const int jr = w * 16 + (t >> 4);
        const int c4 = (t & 15) * 4;
        float4 v = make_float4(sT[jr][c4], sT[jr][c4 + 1], sT[jr][c4 + 2], sT[jr][c4 + 3]);
        __stcs((float4*)(out + ((long long)i * KLEN + (j0 + jr)) * 64 + c4), v);
    }
}

// ---------------- launch ----------------
extern "C" void kernel_launch(void* const* d_in, const int* in_sizes, int n_in,
                              void* d_out, int out_size)
{
    const float* q   = (const float*)d_in[0];
    const float* whk = (const float*)d_in[1];
    const float* r   = (const float*)d_in[2];
    const float* Wr  = (const float*)d_in[3];
    const float* rwb = (const float*)d_in[4];
    const float* rrb = (const float*)d_in[5];
    float* out = (float*)d_out;
    (void)in_sizes; (void)n_in; (void)out_size;

    float *p_rhk4;
    __half *p_Ah, *p_Bh, *p_B16, *p_r2h, *p_Wr2h;
    cudaGetSymbolAddress((void**)&p_rhk4, g_rhk4);
    cudaGetSymbolAddress((void**)&p_B16,  g_B16);
    cudaGetSymbolAddress((void**)&p_Ah,   g_Ah);
    cudaGetSymbolAddress((void**)&p_Bh,   g_Bh);
    cudaGetSymbolAddress((void**)&p_r2h,  g_r2h);
    cudaGetSymbolAddress((void**)&p_Wr2h, g_Wr2h);

    cudaFuncSetAttribute(gemm_b128, cudaFuncAttributeMaxDynamicSharedMemorySize, GB_SMEM);
    cudaFuncSetAttribute(gemm_rhk,  cudaFuncAttributeMaxDynamicSharedMemorySize, RHK_SMEM);

    // 1) all conversions + C bias (one launch)
    conv_all<<<9216, 256>>>(r, Wr, q, whk, rwb);

    // 2) rhk = r.Wr^T, fp16 double-split, split-K=4
    gemm_rhk<<<dim3(DMODEL / 128, KLEN / 128, KSPLIT), 256, RHK_SMEM>>>(
        p_r2h, p_Wr2h, p_rhk4);

    // 3) split-K reduce + fp16 split + D bias
    reduce4_conv_bias<<<KLEN, 256>>>(rrb);

    // 4) B[n][(i,b)][j] fp16 out (per head: M=4096, N=2048, K=128; 8 B tiles/CTA)
    gemm_b128<<<dim3(KLEN / (128 * NT), MROWS / 128, NHEAD), 256, GB_SMEM>>>(
        p_Ah, p_Bh, p_B16);

    // 5) rel-shift gather + bias + transpose
    shuffle_kernel<<<dim3(KLEN / 64, QLEN), 256>>>(out);
}

// round 16
// speedup vs baseline: 2.7112x; 1.0806x over previous
#include <cuda_runtime.h>
#include <cuda_bf16.h>
#include <cuda_fp16.h>
#include <cstdint>

#define QLEN   1024
#define KLEN   2048
#define NHEAD  16
#define DHEAD  64
#define BSZ    4
#define DMODEL 1024
#define MROWS  (QLEN * BSZ)   // 4096 merged (i,b) rows
#define KH2BIG 2048           // 2*DMODEL (fp16 double-split rhk GEMM)
#define KSPLIT 4
#define KSLAB2 (KH2BIG / KSPLIT)  // 512
#define KH2    128            // 2*DHEAD (fp16 double-split gemm-B)

// ---------------- scratch ----------------
__device__ float g_rhk4[(size_t)KSPLIT * KLEN * DMODEL];      // split-K slabs (32MB)
__device__ __half g_B16[(size_t)NHEAD * MROWS * KLEN];        // B [n][(i,b)][j] fp16 (256MB)
__device__ float g_C[KLEN * NHEAD];
__device__ float g_D[KLEN * NHEAD];
__device__ __half g_Ah[(size_t)NHEAD * MROWS * KH2];          // q fp16:   [n][(i,b)][hi64|lo64]
__device__ __half g_Bh[(size_t)NHEAD * KLEN * KH2];           // rhk fp16: [n][j][hi64|lo64]
__device__ __half g_r2h[(size_t)KLEN * KH2BIG];               // r fp16:   [j][hi1024|lo1024]
__device__ __half g_Wr2h[(size_t)DMODEL * KH2BIG];            // W_r fp16: [nd][hi1024|lo1024]

__device__ __forceinline__ void cp_async16(uint32_t smem, const void* gptr) {
    asm volatile("cp.async.ca.shared.global [%0], [%1], 16;" :: "r"(smem), "l"(gptr));
}

// ================= gemm-B: K=128, A-resident, 8 B-tiles per CTA =================
// Epilogue stages acc through the just-consumed B smem buffer so global stores
// are fully-coalesced 16B uint4 (was scattered 4B half2 -> L1 74% bound).
#define SPB 136   // smem row stride fp16 (68 words): conflict-free ldmatrix/STS; 272B = 17*16 aligned
#define NT  8     // B tiles per CTA
#define TILE_U16 (128 * SPB)
#define GB_SMEM (3 * TILE_U16 * 2)   // A + 2 B buffers = 104448 B

__global__ __launch_bounds__(256)
void gemm_b128(const __half* __restrict__ Ag, const __half* __restrict__ Bg,
               __half* __restrict__ Cg)
{
    extern __shared__ __align__(16) uint16_t sm[];

    const int head = blockIdx.z;
    const __half* A  = Ag + (size_t)head * MROWS * KH2 + (blockIdx.y << 7) * KH2;
    const __half* Bb = Bg + (size_t)head * KLEN  * KH2 + (size_t)(blockIdx.x * (128 * NT)) * KH2;
    __half* Cout = Cg + (size_t)head * MROWS * KLEN
                      + (size_t)(blockIdx.y << 7) * KLEN + blockIdx.x * (128 * NT);

    const int t    = threadIdx.x;
    const int lane = t & 31;
    const int wid  = t >> 5;
    const int wm   = (wid & 1) * 64;
    const int wn   = (wid >> 1) * 32;

    const uint32_t s_u32 = (uint32_t)__cvta_generic_to_shared(sm);
    const int srow = t >> 4, sc8 = (t & 15) << 3;   // 8 chunks per thread per tile

    auto issueB = [&](int nt, int buf) {
        const uint32_t sB = s_u32 + (uint32_t)((1 + buf) * TILE_U16) * 2;
        const __half* Bt = Bb + (size_t)(nt * 128) * KH2;
#pragma unroll
        for (int u = 0; u < 8; u++) {
            int row = srow + u * 16;
            cp_async16(sB + (uint32_t)(row * SPB + sc8) * 2, Bt + (size_t)row * KH2 + sc8);
        }
    };

#pragma unroll
    for (int u = 0; u < 8; u++) {
        int row = srow + u * 16;
        cp_async16(s_u32 + (uint32_t)(row * SPB + sc8) * 2, A + (size_t)row * KH2 + sc8);
    }
    issueB(0, 0);
    asm volatile("cp.async.commit_group;");
    issueB(1, 1);
    asm volatile("cp.async.commit_group;");

    const int arow = lane & 15;
    const int acol = (lane >> 4) << 3;
    const int brow = (lane & 7) + ((lane >> 4) << 3);
    const int bcol = ((lane >> 3) & 1) << 3;

    for (int nt = 0; nt < NT; nt++) {
        asm volatile("cp.async.wait_group 1;");
        __syncthreads();

        const int buf = nt & 1;
        const uint32_t sB = s_u32 + (uint32_t)((1 + buf) * TILE_U16) * 2;
        uint16_t* stg = sm + (1 + buf) * TILE_U16;

        float acc[4][4][4];
#pragma unroll
        for (int f = 0; f < 4; f++)
#pragma unroll
            for (int g = 0; g < 4; g++)
#pragma unroll
                for (int c = 0; c < 4; c++) acc[f][g][c] = 0.f;

#pragma unroll
        for (int ks = 0; ks < 128; ks += 16) {
            uint32_t af[4][4], bp[2][4];
#pragma unroll
            for (int f = 0; f < 4; f++) {
                uint32_t addr = s_u32 + (uint32_t)(((wm + f * 16 + arow) * SPB + ks + acol) * 2);
                asm volatile("ldmatrix.sync.aligned.m8n8.x4.shared.b16 {%0,%1,%2,%3}, [%4];"
                    : "=r"(af[f][0]), "=r"(af[f][1]), "=r"(af[f][2]), "=r"(af[f][3])
                    : "r"(addr));
            }
#pragma unroll
            for (int gp = 0; gp < 2; gp++) {
                uint32_t addr = sB + (uint32_t)(((wn + gp * 16 + brow) * SPB + ks + bcol) * 2);
                asm volatile("ldmatrix.sync.aligned.m8n8.x4.shared.b16 {%0,%1,%2,%3}, [%4];"
                    : "=r"(bp[gp][0]), "=r"(bp[gp][1]), "=r"(bp[gp][2]), "=r"(bp[gp][3])
                    : "r"(addr));
            }
#pragma unroll
            for (int f = 0; f < 4; f++)
#pragma unroll
                for (int g = 0; g < 4; g++)
                    asm volatile(
                        "mma.sync.aligned.m16n8k16.row.col.f32.f16.f16.f32 "
                        "{%0,%1,%2,%3}, {%4,%5,%6,%7}, {%8,%9}, {%0,%1,%2,%3};"
                        : "+f"(acc[f][g][0]), "+f"(acc[f][g][1]),
                          "+f"(acc[f][g][2]), "+f"(acc[f][g][3])
                        : "r"(af[f][0]), "r"(af[f][1]), "r"(af[f][2]), "r"(af[f][3]),
                          "r"(bp[g >> 1][(g & 1) * 2]), "r"(bp[g >> 1][(g & 1) * 2 + 1]));
        }
        __syncthreads();   // all warps done reading this B buffer

        // stage acc -> consumed B buffer (STS banks: 68r+c/2, all 32 distinct)
#pragma unroll
        for (int f = 0; f < 4; f++) {
            const int r = wm + f * 16 + (lane >> 2);
#pragma unroll
            for (int g = 0; g < 4; g++) {
                const int c = wn + g * 8 + ((lane & 3) << 1);
                *(__half2*)(stg + r * SPB + c)       = __floats2half2_rn(acc[f][g][0], acc[f][g][1]);
                *(__half2*)(stg + (r + 8) * SPB + c) = __floats2half2_rn(acc[f][g][2], acc[f][g][3]);
            }
        }
        __syncthreads();

        // coalesced 16B stores: warp covers 2 full 256B rows per iteration
        __half* Ct = Cout + nt * 128;
#pragma unroll
        for (int u = 0; u < 8; u++) {
            int idx = t + u * 256;
            int row = idx >> 4, c8 = (idx & 15) << 3;
            uint4 v = *(const uint4*)(stg + row * SPB + c8);
            *(uint4*)(Ct + (size_t)row * KLEN + c8) = v;
        }
        __syncthreads();   // staging reads done before prefetch overwrites

        if (nt + 2 < NT) issueB(nt + 2, buf);
        asm volatile("cp.async.commit_group;");
    }
}

// ================= rhk GEMM: 3-stage cp.async pipeline, BK=32 =================
#define SPAD 40
#define STAGE_U16 (128 * SPAD)
#define RHK_SMEM  (6 * STAGE_U16 * 2)          // 61440 B

__global__ __launch_bounds__(256)
void gemm_rhk(const __half* __restrict__ Ag, const __half* __restrict__ Bg,
              float* __restrict__ Cg)
{
    extern __shared__ __align__(16) uint16_t sm[];

    const __half* A = Ag + (long long)blockIdx.z * KSLAB2 + (blockIdx.y << 7) * KH2BIG;
    const __half* B = Bg + (long long)blockIdx.z * KSLAB2 + (blockIdx.x << 7) * KH2BIG;
    float* Cout = Cg + (long long)blockIdx.z * KLEN * DMODEL
                     + (long long)(blockIdx.y << 7) * DMODEL + (blockIdx.x << 7);

    const int t    = threadIdx.x;
    const int lane = t & 31;
    const int wid  = t >> 5;
    const int wm   = (wid & 1) * 64;
    const int wn   = (wid >> 1) * 32;
    const int nchunk = KSLAB2 / 32;   // 16

    const uint32_t s_u32 = (uint32_t)__cvta_generic_to_shared(sm);
    const int srow = t >> 2, sc8 = (t & 3) << 3;

    auto issue = [&](int kc) {
        const int st = kc % 3;
        const uint32_t sA = s_u32 + (uint32_t)(st * STAGE_U16) * 2;
        const uint32_t sB = s_u32 + (uint32_t)((3 + st) * STAGE_U16) * 2;
        const int ko = kc << 5;
#pragma unroll
        for (int u = 0; u < 2; u++) {
            int row = srow + u * 64;
            cp_async16(sA + (uint32_t)(row * SPAD + sc8) * 2, A + (long long)row * KH2BIG + ko + sc8);
            cp_async16(sB + (uint32_t)(row * SPAD + sc8) * 2, B + (long long)row * KH2BIG + ko + sc8);
        }
    };

    const int arow = lane & 15;
    const int acol = (lane >> 4) << 3;
    const int brow = (lane & 7) + ((lane >> 4) << 3);
    const int bcol = ((lane >> 3) & 1) << 3;

    float acc[4][4][4];
#pragma unroll
    for (int f = 0; f < 4; f++)
#pragma unroll
        for (int g = 0; g < 4; g++)
#pragma unroll
            for (int c = 0; c < 4; c++) acc[f][g][c] = 0.f;

    issue(0); asm volatile("cp.async.commit_group;");
    issue(1); asm volatile("cp.async.commit_group;");

    for (int kc = 0; kc < nchunk; kc++) {
        asm volatile("cp.async.wait_group 1;");
        __syncthreads();

        const int st = kc % 3;
        const uint32_t sA = s_u32 + (uint32_t)(st * STAGE_U16) * 2;
        const uint32_t sB = s_u32 + (uint32_t)((3 + st) * STAGE_U16) * 2;

#pragma unroll
        for (int ks = 0; ks < 32; ks += 16) {
            uint32_t af[4][4], bp[2][4];
#pragma unroll
            for (int f = 0; f < 4; f++) {
                uint32_t addr = sA + (uint32_t)(((wm + f * 16 + arow) * SPAD + ks + acol) * 2);
                asm volatile("ldmatrix.sync.aligned.m8n8.x4.shared.b16 {%0,%1,%2,%3}, [%4];"
                    : "=r"(af[f][0]), "=r"(af[f][1]), "=r"(af[f][2]), "=r"(af[f][3])
                    : "r"(addr));
            }
#pragma unroll
            for (int gp = 0; gp < 2; gp++) {
                uint32_t addr = sB + (uint32_t)(((wn + gp * 16 + brow) * SPAD + ks + bcol) * 2);
                asm volatile("ldmatrix.sync.aligned.m8n8.x4.shared.b16 {%0,%1,%2,%3}, [%4];"
                    : "=r"(bp[gp][0]), "=r"(bp[gp][1]), "=r"(bp[gp][2]), "=r"(bp[gp][3])
                    : "r"(addr));
            }
#pragma unroll
            for (int f = 0; f < 4; f++)
#pragma unroll
                for (int g = 0; g < 4; g++)
                    asm volatile(
                        "mma.sync.aligned.m16n8k16.row.col.f32.f16.f16.f32 "
                        "{%0,%1,%2,%3}, {%4,%5,%6,%7}, {%8,%9}, {%0,%1,%2,%3};"
                        : "+f"(acc[f][g][0]), "+f"(acc[f][g][1]),
                          "+f"(acc[f][g][2]), "+f"(acc[f][g][3])
                        : "r"(af[f][0]), "r"(af[f][1]), "r"(af[f][2]), "r"(af[f][3]),
                          "r"(bp[g >> 1][(g & 1) * 2]), "r"(bp[g >> 1][(g & 1) * 2 + 1]));
        }
        __syncthreads();
        if (kc + 2 < nchunk) issue(kc + 2);
        asm volatile("cp.async.commit_group;");
    }

#pragma unroll
    for (int f = 0; f < 4; f++) {
        const int r = wm + f * 16 + (lane >> 2);
#pragma unroll
        for (int g = 0; g < 4; g++) {
            const int c = wn + g * 8 + ((lane & 3) << 1);
            *(float2*)(Cout + (long long)r * DMODEL + c)       = make_float2(acc[f][g][0], acc[f][g][1]);
            *(float2*)(Cout + (long long)(r + 8) * DMODEL + c) = make_float2(acc[f][g][2], acc[f][g][3]);
        }
    }
}

// ---------------- fused: split-K reduce + fp16 split + D bias ----------------
__global__ __launch_bounds__(256) void reduce4_conv_bias(const float* __restrict__ rrb) {
    const int j = blockIdx.x;
    const int t = threadIdx.x;
    const size_t i = (size_t)j * 1024 + t * 4;
    float4 a = *(const float4*)&g_rhk4[i];
    float4 b = *(const float4*)&g_rhk4[i + (size_t)KLEN * DMODEL];
    float4 c = *(const float4*)&g_rhk4[i + (size_t)2 * KLEN * DMODEL];
    float4 d = *(const float4*)&g_rhk4[i + (size_t)3 * KLEN * DMODEL];
    float v[4] = {a.x + b.x + c.x + d.x, a.y + b.y + c.y + d.y,
                  a.z + b.z + c.z + d.z, a.w + b.w + c.w + d.w};

    const int e = t * 4;
    const int n = e >> 6, d0 = e & 63;
    __half* dst = g_Bh + ((size_t)n * KLEN + j) * KH2;
    __half hi[4], lo[4];
    float sd = 0.f;
#pragma unroll
    for (int u = 0; u < 4; u++) {
        hi[u] = __float2half_rn(v[u]);
        lo[u] = __float2half_rn(v[u] - __half2float(hi[u]));
        sd += v[u] * rrb[n * DHEAD + d0 + u];
    }
    *(__half2*)(dst + d0)          = __halves2half2(hi[0], hi[1]);
    *(__half2*)(dst + d0 + 2)      = __halves2half2(hi[2], hi[3]);
    *(__half2*)(dst + 64 + d0)     = __halves2half2(lo[0], lo[1]);
    *(__half2*)(dst + 64 + d0 + 2) = __halves2half2(lo[2], lo[3]);

#pragma unroll
    for (int o = 8; o > 0; o >>= 1)
        sd += __shfl_xor_sync(0xffffffffu, sd, o);
    if ((t & 15) == 0) g_D[j * NHEAD + n] = sd;
}

// ---------------- fused conversions + C bias ----------------
__global__ __launch_bounds__(256)
void conv_all(const float* __restrict__ r, const float* __restrict__ Wr,
              const float* __restrict__ q, const float* __restrict__ whk,
              const float* __restrict__ rwb)
{
    const int blk = blockIdx.x;
    const int t = threadIdx.x;
    if (blk < 7168) {
        const float* in;
        int row;
        if (blk < 2048)      { in = r;  row = blk; }
        else if (blk < 3072) { in = Wr; row = blk - 2048; }
        else                 { in = q;  row = blk - 3072; }
#pragma unroll
        for (int it = 0; it < 4; it++) {
            int e = t + it * 256;
            float x = in[(size_t)row * 1024 + e];
            __half hi = __float2half_rn(x);
            __half lo = __float2half_rn(x - __half2float(hi));
            if (blk < 3072) {
                __half* dst = (blk < 2048 ? g_r2h : g_Wr2h) + (size_t)row * KH2BIG;
                dst[e] = hi;
                dst[1024 + e] = lo;
            } else {
                int n = e >> 6, dd = e & 63;
                __half* dst = g_Ah + ((size_t)n * MROWS + row) * KH2;
                dst[dd] = hi;
                dst[64 + dd] = lo;
            }
        }
    } else {
        // C[j][n] = sum_{b,d} rwb[n,d] * whk[j,b,n,d]; whk row j = 4096 floats
        const int j = blk - 7168;
        const int n = t >> 4, s = t & 15;
        const float* row = whk + (size_t)j * (BSZ * NHEAD * DHEAD);
        float sum = 0.f;
#pragma unroll
        for (int k = 0; k < 16; k++) {
            int e = s + k * 16;           // e enumerates (b,d): b = e>>6, d = e&63
            sum += rwb[n * DHEAD + (e & 63)] * row[(e >> 6) * (NHEAD * DHEAD) + n * DHEAD + (e & 63)];
        }
#pragma unroll
        for (int o = 8; o > 0; o >>= 1)
            sum += __shfl_xor_sync(0xffffffffu, sum, o);
        if (s == 0) g_C[j * NHEAD + n] = sum;
    }
}

// ---------------- rel_shift gather + bias add + (b,n) transpose ----------------
__global__ __launch_bounds__(256)
void shuffle_kernel(float* __restrict__ out)
{
    __shared__ float sT[64][65];
    __shared__ float sCD[64][17];
    __shared__ int   sIpB[64];
    __shared__ int   sJq[64];

    const int t  = threadIdx.x;
    const int i  = blockIdx.y;
    const int j0 = blockIdx.x * 64;

    for (int idx = t; idx < 64 * NHEAD; idx += 256) {
        const int jl = idx >> 4;
        const int n  = idx & 15;
        const int j  = j0 + jl;
        const int pos = i * KLEN + j + QLEN;
        const int ip  = pos / (KLEN + 1);
        const int jp  = pos - ip * (KLEN + 1);
        float v = g_C[j * NHEAD + n];
        if (jp != 0) v += g_D[(jp - 1) * NHEAD + n];
        sCD[jl][n] = v;
        if (n == 0) { sIpB[jl] = ip * BSZ; sJq[jl] = jp - 1; }
    }
    __syncthreads();

    const int jj = t & 31;
    const int cb = t >> 5;

#pragma unroll
    for (int jc = 0; jc < 2; jc++) {
        const int jl  = jc * 32 + jj;
        const int jq  = sJq[jl];
        const int ipb = sIpB[jl];
#pragma unroll
        for (int u = 0; u < 8; u++) {
            const int c = cb + u * 8;   // c = b*16 + n
            const int b = c >> 4;
            const int n = c & 15;
            float v = sCD[jl][n];
            if (jq >= 0)
                v += __half2float(__ldcs(&g_B16[((size_t)n * MROWS + ipb + b) * KLEN + jq]));
            sT[jl][c] = v;
        }
    }
    __syncthreads();

#pragma unroll
    for (int w = 0; w < 4; w++) {
        const int jr = w * 16 + (t >> 4);
        const int c4 = (t & 15) * 4;
        float4 v = make_float4(sT[jr][c4], sT[jr][c4 + 1], sT[jr][c4 + 2], sT[jr][c4 + 3]);
        __stcs((float4*)(out + ((long long)i * KLEN + (j0 + jr)) * 64 + c4), v);
    }
}

// ---------------- launch ----------------
extern "C" void kernel_launch(void* const* d_in, const int* in_sizes, int n_in,
                              void* d_out, int out_size)
{
    const float* q   = (const float*)d_in[0];
    const float* whk = (const float*)d_in[1];
    const float* r   = (const float*)d_in[2];
    const float* Wr  = (const float*)d_in[3];
    const float* rwb = (const float*)d_in[4];
    const float* rrb = (const float*)d_in[5];
    float* out = (float*)d_out;
    (void)in_sizes; (void)n_in; (void)out_size;

    float *p_rhk4;
    __half *p_Ah, *p_Bh, *p_B16, *p_r2h, *p_Wr2h;
    cudaGetSymbolAddress((void**)&p_rhk4, g_rhk4);
    cudaGetSymbolAddress((void**)&p_B16,  g_B16);
    cudaGetSymbolAddress((void**)&p_Ah,   g_Ah);
    cudaGetSymbolAddress((void**)&p_Bh,   g_Bh);
    cudaGetSymbolAddress((void**)&p_r2h,  g_r2h);
    cudaGetSymbolAddress((void**)&p_Wr2h, g_Wr2h);

    cudaFuncSetAttribute(gemm_b128, cudaFuncAttributeMaxDynamicSharedMemorySize, GB_SMEM);
    cudaFuncSetAttribute(gemm_rhk,  cudaFuncAttributeMaxDynamicSharedMemorySize, RHK_SMEM);

    // 1) all conversions + C bias (one launch)
    conv_all<<<9216, 256>>>(r, Wr, q, whk, rwb);

    // 2) rhk = r.Wr^T, fp16 double-split, split-K=4
    gemm_rhk<<<dim3(DMODEL / 128, KLEN / 128, KSPLIT), 256, RHK_SMEM>>>(
        p_r2h, p_Wr2h, p_rhk4);

    // 3) split-K reduce + fp16 split + D bias
    reduce4_conv_bias<<<KLEN, 256>>>(rrb);

    // 4) B[n][(i,b)][j] fp16 out (per head: M=4096, N=2048, K=128; 8 B tiles/CTA)
    gemm_b128<<<dim3(KLEN / (128 * NT), MROWS / 128, NHEAD), 256, GB_SMEM>>>(
        p_Ah, p_Bh, p_B16);

    // 5) rel-shift gather + bias + transpose
    shuffle_kernel<<<dim3(KLEN / 64, QLEN), 256>>>(out);
}